// round 1
// baseline (speedup 1.0000x reference)
#include <cuda_runtime.h>
#include <cstdint>
#include <cstdio>

// Problem constants
constexpr int CB  = 2;     // batch
constexpr int CL  = 4096;  // seq len
constexpr int CDM = 768;   // d_model
constexpr int CDI = 1536;  // d_inner
constexpr int CN  = 16;    // state dim
constexpr int CR  = 48;    // dt rank
constexpr int CK  = 4;     // conv width
constexpr int CPROJ = CR + 2*CN; // 80

// ---------------------------------------------------------------------------
// Scratch (device globals; no runtime allocation allowed)
// ---------------------------------------------------------------------------
__device__ float g_xz[CB * 2 * CDI * CL];        // (b, e, l)   e in [0,3072)
__device__ float g_xt[2][CB * CL * CDI];         // per dir, (b, t, d)
__device__ float g_dbl[2][CB * CL * CPROJ];      // per dir, (b*L, 80): dt|B|C
__device__ float g_delta[2][CB * CL * CDI];      // per dir, (b, t, d) post-softplus
__device__ float g_y[2][CB * CL * CDI];          // per dir, (b, t, d) scan out (+D*x)
__device__ float g_comb[CB * CL * CDI];          // gated sum, (b, l, d)

// ---------------------------------------------------------------------------
// Generic fp32 NT GEMM: C[m,n] = sum_k A[m*K+k] * B[n*K+k]
// 128x128 block, BK=8, 256 threads, 8x8 per thread, reg-prefetch pipeline.
// M,N divisible by 128; K divisible by 8 (holds for all our shapes).
// ---------------------------------------------------------------------------
__global__ void __launch_bounds__(256) gemm_nt_kernel(
    const float* __restrict__ A, const float* __restrict__ B,
    float* __restrict__ C, int M, int N, int Kd,
    long long strideB, long long strideC)
{
    B += (size_t)blockIdx.z * strideB;
    C += (size_t)blockIdx.z * strideC;
    const int bm = blockIdx.y * 128;
    const int bn = blockIdx.x * 128;

    __shared__ __align__(16) float As[8][128];
    __shared__ __align__(16) float Bs[8][128];

    const int tid = threadIdx.x;
    const int ar  = tid >> 1;          // 0..127
    const int ak  = (tid & 1) * 4;     // 0 or 4
    const float* Ap = A + (size_t)(bm + ar) * Kd + ak;
    const float* Bp = B + (size_t)(bn + ar) * Kd + ak;

    const int tx = tid & 15;   // n micro-tile
    const int ty = tid >> 4;   // m micro-tile

    float acc[8][8] = {};
    float4 av = *(const float4*)Ap;
    float4 bv = *(const float4*)Bp;

    const int ntiles = Kd >> 3;
    for (int t = 0; t < ntiles; ++t) {
        As[ak+0][ar] = av.x; As[ak+1][ar] = av.y; As[ak+2][ar] = av.z; As[ak+3][ar] = av.w;
        Bs[ak+0][ar] = bv.x; Bs[ak+1][ar] = bv.y; Bs[ak+2][ar] = bv.z; Bs[ak+3][ar] = bv.w;
        __syncthreads();
        if (t + 1 < ntiles) {
            av = *(const float4*)(Ap + (size_t)(t+1)*8);
            bv = *(const float4*)(Bp + (size_t)(t+1)*8);
        }
#pragma unroll
        for (int k = 0; k < 8; ++k) {
            float4 a0 = *(const float4*)&As[k][ty*8];
            float4 a1 = *(const float4*)&As[k][ty*8+4];
            float4 b0 = *(const float4*)&Bs[k][tx*8];
            float4 b1 = *(const float4*)&Bs[k][tx*8+4];
            float a[8] = {a0.x,a0.y,a0.z,a0.w,a1.x,a1.y,a1.z,a1.w};
            float bb[8] = {b0.x,b0.y,b0.z,b0.w,b1.x,b1.y,b1.z,b1.w};
#pragma unroll
            for (int i = 0; i < 8; ++i)
#pragma unroll
                for (int j = 0; j < 8; ++j)
                    acc[i][j] = fmaf(a[i], bb[j], acc[i][j]);
        }
        __syncthreads();
    }

#pragma unroll
    for (int i = 0; i < 8; ++i) {
        float* crow = C + (size_t)(bm + ty*8 + i) * N + bn + tx*8;
        float4 o0 = {acc[i][0], acc[i][1], acc[i][2], acc[i][3]};
        float4 o1 = {acc[i][4], acc[i][5], acc[i][6], acc[i][7]};
        *(float4*)(crow)     = o0;
        *(float4*)(crow + 4) = o1;
    }
}

// ---------------------------------------------------------------------------
// Depthwise causal conv (K=4) + bias + SiLU, with transpose to (b, t, d).
// dir=0: forward on x; dir=1: causal conv on time-reversed x, output indexed
// by reversed time t (own domain).
// Block: 256 threads; tile = 32 channels x 128 timesteps.
// ---------------------------------------------------------------------------
__global__ void __launch_bounds__(256) conv_silu_kernel(
    const float* __restrict__ cw_f, const float* __restrict__ cb_f,
    const float* __restrict__ cw_b, const float* __restrict__ cb_b)
{
    const int t0 = blockIdx.x * 128;
    const int d0 = blockIdx.y * 32;
    const int b   = blockIdx.z & 1;
    const int dir = blockIdx.z >> 1;

    __shared__ float xs[32][133];   // stride 133: 133%32=5, gcd(5,32)=1 -> conflict-free

    const float* xbase = g_xz + ((size_t)b * (2*CDI) + d0) * CL;
    const int base = (dir == 0) ? (t0 - 3) : (CL - 128 - t0);

    const int lane = threadIdx.x & 31;
    const int wy   = threadIdx.x >> 5;
    for (int d = wy; d < 32; d += 8) {
        const float* row = xbase + (size_t)d * CL;
        for (int i = lane; i < 131; i += 32) {
            int u = base + i;
            xs[d][i] = (u >= 0 && u < CL) ? row[u] : 0.f;
        }
    }
    __syncthreads();

    const int d  = threadIdx.x & 31;
    const int sg = threadIdx.x >> 5;
    const float* cw = dir ? cw_b : cw_f;
    const float* cb = dir ? cb_b : cb_f;
    const float w0 = cw[(d0+d)*CK + 0];
    const float w1 = cw[(d0+d)*CK + 1];
    const float w2 = cw[(d0+d)*CK + 2];
    const float w3 = cw[(d0+d)*CK + 3];
    const float bias = cb[d0+d];

    float* out = g_xt[dir] + (size_t)b * CL * CDI;
#pragma unroll
    for (int q = 0; q < 16; ++q) {
        int s = sg + 8*q;
        float v;
        if (dir == 0) {
            v = w0*xs[d][s] + w1*xs[d][s+1] + w2*xs[d][s+2] + w3*xs[d][s+3] + bias;
        } else {
            // xc_b[t] = sum_j w_b[3-j] * x[(L-1-t)+j]
            v = w3*xs[d][127-s] + w2*xs[d][127-s+1] + w1*xs[d][127-s+2] + w0*xs[d][127-s+3] + bias;
        }
        float sv = v / (1.f + __expf(-v));
        out[(size_t)(t0 + s) * CDI + d0 + d] = sv;
    }
}

// ---------------------------------------------------------------------------
// xproj: dbl[row, r] = sum_d xt[row, d] * W[r, d],  rows=B*L, r<80, K=1536
// Block tile: 128 rows x 80 cols, BK=16. 256 threads, 8x5 micro-tile.
// ---------------------------------------------------------------------------
__global__ void __launch_bounds__(256) xproj_kernel(
    const float* __restrict__ xpw_f, const float* __restrict__ xpw_b)
{
    const int dir = blockIdx.y;
    const float* W = dir ? xpw_b : xpw_f;
    const float* X = g_xt[dir];
    float* O = g_dbl[dir];
    const int r0 = blockIdx.x * 128;

    __shared__ __align__(16) float Xs[16][128];
    __shared__ float Ws[16][80];

    const int tid = threadIdx.x;
    const int tx = tid & 15;   // 5 cols each
    const int ty = tid >> 4;   // 8 rows each
    const int xr = tid >> 1;
    const int xk = (tid & 1) * 8;

    float acc[8][5] = {};

    for (int k0 = 0; k0 < CDI; k0 += 16) {
        float4 v0 = *(const float4*)(X + (size_t)(r0+xr)*CDI + k0 + xk);
        float4 v1 = *(const float4*)(X + (size_t)(r0+xr)*CDI + k0 + xk + 4);
        float wv[5];
#pragma unroll
        for (int p = 0; p < 5; ++p) {
            int idx = tid + p*256;           // 0..1279
            int wr = idx >> 4, wk = idx & 15;
            wv[p] = W[(size_t)wr*CDI + k0 + wk];
        }
        __syncthreads();
        Xs[xk+0][xr]=v0.x; Xs[xk+1][xr]=v0.y; Xs[xk+2][xr]=v0.z; Xs[xk+3][xr]=v0.w;
        Xs[xk+4][xr]=v1.x; Xs[xk+5][xr]=v1.y; Xs[xk+6][xr]=v1.z; Xs[xk+7][xr]=v1.w;
#pragma unroll
        for (int p = 0; p < 5; ++p) {
            int idx = tid + p*256;
            int wr = idx >> 4, wk = idx & 15;
            Ws[wk][wr] = wv[p];
        }
        __syncthreads();
#pragma unroll
        for (int k = 0; k < 16; ++k) {
            float4 a0 = *(const float4*)&Xs[k][ty*8];
            float4 a1 = *(const float4*)&Xs[k][ty*8+4];
            float a[8] = {a0.x,a0.y,a0.z,a0.w,a1.x,a1.y,a1.z,a1.w};
            float w[5];
#pragma unroll
            for (int j = 0; j < 5; ++j) w[j] = Ws[k][tx*5+j];
#pragma unroll
            for (int i = 0; i < 8; ++i)
#pragma unroll
                for (int j = 0; j < 5; ++j)
                    acc[i][j] = fmaf(a[i], w[j], acc[i][j]);
        }
        __syncthreads();
    }
#pragma unroll
    for (int i = 0; i < 8; ++i)
#pragma unroll
        for (int j = 0; j < 5; ++j)
            O[(size_t)(r0 + ty*8 + i)*CPROJ + tx*5 + j] = acc[i][j];
}

// ---------------------------------------------------------------------------
// dtproj + softplus: delta[row, d] = softplus(sum_r dt[row,r]*dtw[d,r] + dtb[d])
// dt = dbl[:, :48].  Block tile: 64 rows x 128 d, K=48 resident.
// ---------------------------------------------------------------------------
__device__ __forceinline__ float softplus_f(float v) {
    return (v > 20.f) ? v : log1pf(__expf(v));
}

__global__ void __launch_bounds__(256) dtproj_kernel(
    const float* __restrict__ dtw_f, const float* __restrict__ dtb_f,
    const float* __restrict__ dtw_b, const float* __restrict__ dtb_b)
{
    const int dir = blockIdx.z;
    const float* W    = dir ? dtw_b : dtw_f;   // (1536, 48)
    const float* bias = dir ? dtb_b : dtb_f;
    const float* DT = g_dbl[dir];              // rows stride 80
    float* O = g_delta[dir];

    const int r0 = blockIdx.x * 64;
    const int d0 = blockIdx.y * 128;

    __shared__ __align__(16) float Ts[48][64];
    __shared__ __align__(16) float Ws2[48][128];

    const int tid = threadIdx.x;
#pragma unroll
    for (int p = 0; p < 3; ++p) {
        int q = tid + p*256;                 // 0..767
        int rr = q / 12, kk = (q % 12) * 4;
        float4 v = *(const float4*)(DT + (size_t)(r0+rr)*CPROJ + kk);
        Ts[kk+0][rr]=v.x; Ts[kk+1][rr]=v.y; Ts[kk+2][rr]=v.z; Ts[kk+3][rr]=v.w;
    }
#pragma unroll
    for (int p = 0; p < 6; ++p) {
        int q = tid + p*256;                 // 0..1535
        int dd = q / 12, kk = (q % 12) * 4;
        float4 v = *(const float4*)(W + (size_t)(d0+dd)*CR + kk);
        Ws2[kk+0][dd]=v.x; Ws2[kk+1][dd]=v.y; Ws2[kk+2][dd]=v.z; Ws2[kk+3][dd]=v.w;
    }
    __syncthreads();

    const int tx = tid & 31;   // 4 d-cols each
    const int ty = tid >> 5;   // 8 rows each
    float acc[8][4] = {};
#pragma unroll
    for (int k = 0; k < 48; ++k) {
        float4 a0 = *(const float4*)&Ts[k][ty*8];
        float4 a1 = *(const float4*)&Ts[k][ty*8+4];
        float a[8] = {a0.x,a0.y,a0.z,a0.w,a1.x,a1.y,a1.z,a1.w};
        float4 w = *(const float4*)&Ws2[k][tx*4];
        float ww[4] = {w.x, w.y, w.z, w.w};
#pragma unroll
        for (int i = 0; i < 8; ++i)
#pragma unroll
            for (int j = 0; j < 4; ++j)
                acc[i][j] = fmaf(a[i], ww[j], acc[i][j]);
    }

    const int tx4 = tx*4;
    float b0 = bias[d0+tx4+0], b1 = bias[d0+tx4+1], b2 = bias[d0+tx4+2], b3 = bias[d0+tx4+3];
#pragma unroll
    for (int i = 0; i < 8; ++i) {
        float4 v;
        v.x = softplus_f(acc[i][0] + b0);
        v.y = softplus_f(acc[i][1] + b1);
        v.z = softplus_f(acc[i][2] + b2);
        v.w = softplus_f(acc[i][3] + b3);
        *(float4*)(O + (size_t)(r0 + ty*8 + i)*CDI + d0 + tx4) = v;
    }
}

// ---------------------------------------------------------------------------
// Selective scan. One warp = 2 channels x 16 states (lane = half*16 + n).
// Block = 8 warps = 16 channels of one (b, dir). Chunked smem staging (64
// steps) with register prefetch of the next chunk to hide HBM latency.
// h_{t} = exp(delta_t * A[d,n]) * h_{t-1} + delta_t * x_t * B_t[n]
// y_t[d] = sum_n h_t[d,n] * C_t[n]  + x_t * D[d]
// ---------------------------------------------------------------------------
__global__ void __launch_bounds__(256) scan_kernel(
    const float* __restrict__ Alog_f, const float* __restrict__ Dv_f,
    const float* __restrict__ Alog_b, const float* __restrict__ Dv_b)
{
    const int dir = blockIdx.z;
    const int b   = blockIdx.y;
    const int d0  = blockIdx.x * 16;

    const float* Alog = dir ? Alog_b : Alog_f;
    const float* Dvec = dir ? Dv_b   : Dv_f;
    const float* delta = g_delta[dir] + (size_t)b * CL * CDI;
    const float* xt    = g_xt[dir]    + (size_t)b * CL * CDI;
    const float* dbl   = g_dbl[dir]   + (size_t)b * CL * CPROJ;
    float* yout        = g_y[dir]     + (size_t)b * CL * CDI;

    __shared__ __align__(16) float sd[64][16];
    __shared__ __align__(16) float sx[64][16];
    __shared__ __align__(16) float sB[64][16];
    __shared__ __align__(16) float sC[64][16];

    const int tid  = threadIdx.x;
    const int lane = tid & 31;
    const int wid  = tid >> 5;
    const int half = lane >> 4;
    const int n    = lane & 15;
    const int ch   = wid*2 + half;   // 0..15
    const int d    = d0 + ch;

    const float Aval = -__expf(Alog[d*CN + n]);
    const float Dval = Dvec[d];
    float h = 0.f;

    const int li = tid >> 2;          // chunk row 0..63
    const int lj = (tid & 3) * 4;     // 0,4,8,12

    float4 rd, rx, rB, rC;
    auto LD = [&](int t0) {
        rd = *(const float4*)(delta + (size_t)(t0+li)*CDI + d0 + lj);
        rx = *(const float4*)(xt    + (size_t)(t0+li)*CDI + d0 + lj);
        rB = *(const float4*)(dbl + (size_t)(t0+li)*CPROJ + CR + lj);
        rC = *(const float4*)(dbl + (size_t)(t0+li)*CPROJ + CR + CN + lj);
    };
    LD(0);

    const int NCH = CL / 64;
    for (int c = 0; c < NCH; ++c) {
        __syncthreads();
        *(float4*)&sd[li][lj] = rd;
        *(float4*)&sx[li][lj] = rx;
        *(float4*)&sB[li][lj] = rB;
        *(float4*)&sC[li][lj] = rC;
        __syncthreads();
        if (c + 1 < NCH) LD((c+1) * 64);

        const int tbase = c * 64;
#pragma unroll 8
        for (int s = 0; s < 64; ++s) {
            float dt = sd[s][ch];
            float xv = sx[s][ch];
            float Bv = sB[s][n];
            float Cv = sC[s][n];
            float a = __expf(dt * Aval);
            h = fmaf(a, h, dt * xv * Bv);
            float p = h * Cv;
            p += __shfl_xor_sync(0xffffffffu, p, 8);
            p += __shfl_xor_sync(0xffffffffu, p, 4);
            p += __shfl_xor_sync(0xffffffffu, p, 2);
            p += __shfl_xor_sync(0xffffffffu, p, 1);
            if (n == 0)
                yout[(size_t)(tbase + s)*CDI + d] = p + xv * Dval;
        }
    }
}

// ---------------------------------------------------------------------------
// Gate + direction merge: comb[b,l,d] = (yf[b,l,d] + yb[b,L-1-l,d]) * silu(z[b,d,l])
// z comes from g_xz channels [DI, 2*DI); transposed read via smem tile.
// ---------------------------------------------------------------------------
__global__ void __launch_bounds__(256) combine_kernel()
{
    const int l0 = blockIdx.x * 32;
    const int d0 = blockIdx.y * 32;
    const int b  = blockIdx.z;

    __shared__ float zs[32][33];
    const int lane = threadIdx.x & 31;
    const int wy   = threadIdx.x >> 5;

    const float* zbase = g_xz + ((size_t)b * (2*CDI) + CDI + d0) * CL;
    for (int dd = wy; dd < 32; dd += 8)
        zs[dd][lane] = zbase[(size_t)dd * CL + l0 + lane];
    __syncthreads();

#pragma unroll
    for (int q = 0; q < 4; ++q) {
        int lr = wy + 8*q;
        int l = l0 + lr;
        size_t idx  = ((size_t)b*CL + l)*CDI + d0 + lane;
        size_t idxr = ((size_t)b*CL + (CL-1-l))*CDI + d0 + lane;
        float yf = g_y[0][idx];
        float yb = g_y[1][idxr];
        float zv = zs[lane][lr];
        float s = zv / (1.f + __expf(-zv));
        g_comb[idx] = (yf + yb) * s;
    }
}

// ---------------------------------------------------------------------------
// Launcher
// ---------------------------------------------------------------------------
extern "C" void kernel_launch(void* const* d_in, const int* in_sizes, int n_in,
                              void* d_out, int out_size)
{
    (void)in_sizes; (void)n_in; (void)out_size;

    const float* hidden  = (const float*)d_in[0];
    const float* in_w    = (const float*)d_in[1];
    const float* conv_w  = (const float*)d_in[2];
    const float* conv_b  = (const float*)d_in[3];
    const float* xproj_w = (const float*)d_in[4];
    const float* dtw     = (const float*)d_in[5];
    const float* dtb     = (const float*)d_in[6];
    const float* A_log   = (const float*)d_in[7];
    const float* Dv      = (const float*)d_in[8];
    const float* conv_w2 = (const float*)d_in[9];
    const float* conv_b2 = (const float*)d_in[10];
    const float* xproj_w2= (const float*)d_in[11];
    const float* dtw2    = (const float*)d_in[12];
    const float* dtb2    = (const float*)d_in[13];
    const float* A_log2  = (const float*)d_in[14];
    const float* Dv2     = (const float*)d_in[15];
    const float* out_w   = (const float*)d_in[16];

    void* p_xz = nullptr;
    void* p_comb = nullptr;
    cudaGetSymbolAddress(&p_xz, g_xz);
    cudaGetSymbolAddress(&p_comb, g_comb);

    // 1) in_proj: xz[b,e,l] = sum_d W[e,d] * hidden[b,l,d]
    //    M=3072 (e), N=4096 (l), K=768; batched over b.
    gemm_nt_kernel<<<dim3(CL/128, (2*CDI)/128, CB), 256>>>(
        in_w, hidden, (float*)p_xz, 2*CDI, CL, CDM,
        (long long)CL * CDM, (long long)(2*CDI) * CL);

    // 2) conv + SiLU + transpose (both batches, both directions)
    conv_silu_kernel<<<dim3(CL/128, CDI/32, 2*CB), 256>>>(
        conv_w, conv_b, conv_w2, conv_b2);

    // 3) xproj -> dbl (dt|B|C)
    xproj_kernel<<<dim3((CB*CL)/128, 2), 256>>>(xproj_w, xproj_w2);

    // 4) dtproj + softplus -> delta
    dtproj_kernel<<<dim3((CB*CL)/64, CDI/128, 2), 256>>>(dtw, dtb, dtw2, dtb2);

    // 5) selective scan (both dirs, both batches)
    scan_kernel<<<dim3(CDI/16, CB, 2), 256>>>(A_log, Dv, A_log2, Dv2);

    // 6) gate + direction merge
    combine_kernel<<<dim3(CL/32, CDI/32, CB), 256>>>();

    // 7) out_proj: out[b,l,o] = sum_d comb[b,l,d] * W[o,d]
    //    M=8192 rows (b*L+l), N=768 (o), K=1536.
    gemm_nt_kernel<<<dim3(CDM/128, (CB*CL)/128, 1), 256>>>(
        (const float*)p_comb, out_w, (float*)d_out, CB*CL, CDM, CDI, 0, 0);
}

// round 3
// speedup vs baseline: 1.4410x; 1.4410x over previous
#include <cuda_runtime.h>
#include <cuda_bf16.h>
#include <cstdint>

// Problem constants
constexpr int CB  = 2;     // batch
constexpr int CL  = 4096;  // seq len
constexpr int CDM = 768;   // d_model
constexpr int CDI = 1536;  // d_inner
constexpr int CN  = 16;    // state dim
constexpr int CR  = 48;    // dt rank
constexpr int CK  = 4;     // conv width
constexpr int CPROJ = CR + 2*CN; // 80

// ---------------------------------------------------------------------------
// Scratch (device globals; no runtime allocation allowed)
// ---------------------------------------------------------------------------
__device__ float g_xz[CB * 2 * CDI * CL];        // (b, e, l)   e in [0,3072)
__device__ float g_xt[2][CB * CL * CDI];         // per dir, (b, t, d)
__device__ float g_dbl[2][CB * CL * CPROJ];      // per dir, (b*L, 80): dt|B|C
__device__ float g_delta[2][CB * CL * CDI];      // per dir, (b, t, d) post-softplus
__device__ float g_y[2][CB * CL * CDI];          // per dir, (b, t, d) scan out (+D*x)
__device__ float g_comb[CB * CL * CDI];          // gated sum, (b, l, d)

// ---------------------------------------------------------------------------
// mma.sync / ldmatrix helpers (Ampere-era PTX; assembles under compute_103)
// ---------------------------------------------------------------------------
__device__ __forceinline__ uint32_t smem_u32(const void* p) {
    uint32_t a;
    asm("{ .reg .u64 t; cvta.to.shared.u64 t, %1; cvt.u32.u64 %0, t; }" : "=r"(a) : "l"(p));
    return a;
}
__device__ __forceinline__ uint32_t sw128(uint32_t b) { return b ^ ((b >> 3) & 0x70); }

__device__ __forceinline__ void ldsm4(uint32_t addr, uint32_t r[4]) {
    asm volatile("ldmatrix.sync.aligned.m8n8.x4.shared.b16 {%0,%1,%2,%3}, [%4];"
        : "=r"(r[0]), "=r"(r[1]), "=r"(r[2]), "=r"(r[3]) : "r"(addr));
}
__device__ __forceinline__ void mma_bf16(float* d, const uint32_t* a, uint32_t b0, uint32_t b1) {
    asm volatile("mma.sync.aligned.m16n8k16.row.col.f32.bf16.bf16.f32 "
        "{%0,%1,%2,%3}, {%4,%5,%6,%7}, {%8,%9}, {%0,%1,%2,%3};"
        : "+f"(d[0]), "+f"(d[1]), "+f"(d[2]), "+f"(d[3])
        : "r"(a[0]), "r"(a[1]), "r"(a[2]), "r"(a[3]), "r"(b0), "r"(b1));
}

// ---------------------------------------------------------------------------
// Tensor-core split-bf16 GEMM:  C[m,n] = sum_k A[m,k]*B[n,k]   (fp32 in/out)
// CTA tile M=128, N=128, BK=64.  3-term bf16 split (hi*hi + hi*lo + lo*hi).
// Double-buffered smem (bf16 hi/lo, SW128 swizzle, 128B rows). LDG for chunk
// c+1 issued before the MMA loop of chunk c; convert+STS after.
// Stage layout (64KB): Ahi 16K | Alo 16K | Bhi 16K | Blo 16K.
// ---------------------------------------------------------------------------
constexpr int TC_STAGE = 65536;
constexpr int TC_SMEM  = 2 * TC_STAGE;   // 131072 B

__global__ void __launch_bounds__(256) gemm_tc_kernel(
    const float* __restrict__ A, const float* __restrict__ B, float* __restrict__ C,
    int N, int Kd, long long strideB, long long strideC, int NC)
{
    extern __shared__ __align__(1024) char smem[];
    const uint32_t su = smem_u32(smem);
    B += (size_t)blockIdx.z * strideB;
    C += (size_t)blockIdx.z * strideC;
    const int bm = blockIdx.y * 128;
    const int bn = blockIdx.x * 128;
    const int tid  = threadIdx.x;
    const int wid  = tid >> 5;
    const int lane = tid & 31;

    // producer addressing: 8 float4 per thread for each of A and B
    const int prow = tid >> 1;              // handled differently below
    (void)prow;

    float4 rA[8], rB[8];
    auto LDG = [&](int c) {
        const int k0 = c * 64;
#pragma unroll
        for (int i = 0; i < 8; ++i) {
            int idx = tid + i * 256;
            int row = idx >> 4, kq = idx & 15;
            rA[i] = *(const float4*)(A + (size_t)(bm + row) * Kd + k0 + kq * 4);
            rB[i] = *(const float4*)(B + (size_t)(bn + row) * Kd + k0 + kq * 4);
        }
    };
    auto STS = [&](int s) {
        char* sb = smem + s * TC_STAGE;
#pragma unroll
        for (int i = 0; i < 8; ++i) {
            int idx = tid + i * 256;
            int row = idx >> 4, kq = idx & 15;
            uint32_t off = sw128((uint32_t)(row * 128 + kq * 8));
            {
                float4 v = rA[i];
                __nv_bfloat162 h01 = __floats2bfloat162_rn(v.x, v.y);
                __nv_bfloat162 h23 = __floats2bfloat162_rn(v.z, v.w);
                __nv_bfloat162 l01 = __floats2bfloat162_rn(v.x - __bfloat162float(h01.x),
                                                           v.y - __bfloat162float(h01.y));
                __nv_bfloat162 l23 = __floats2bfloat162_rn(v.z - __bfloat162float(h23.x),
                                                           v.w - __bfloat162float(h23.y));
                *(uint2*)(sb + off)         = make_uint2(*(uint32_t*)&h01, *(uint32_t*)&h23);
                *(uint2*)(sb + 16384 + off) = make_uint2(*(uint32_t*)&l01, *(uint32_t*)&l23);
            }
            {
                float4 v = rB[i];
                __nv_bfloat162 h01 = __floats2bfloat162_rn(v.x, v.y);
                __nv_bfloat162 h23 = __floats2bfloat162_rn(v.z, v.w);
                __nv_bfloat162 l01 = __floats2bfloat162_rn(v.x - __bfloat162float(h01.x),
                                                           v.y - __bfloat162float(h01.y));
                __nv_bfloat162 l23 = __floats2bfloat162_rn(v.z - __bfloat162float(h23.x),
                                                           v.w - __bfloat162float(h23.y));
                *(uint2*)(sb + 32768 + off) = make_uint2(*(uint32_t*)&h01, *(uint32_t*)&h23);
                *(uint2*)(sb + 49152 + off) = make_uint2(*(uint32_t*)&l01, *(uint32_t*)&l23);
            }
        }
    };

    // warp tiling: 4x2 warps, warp tile 32 (m) x 64 (n)
    const int m0 = (wid & 3) * 32;
    const int n0 = (wid >> 2) * 64;

    // ldmatrix lane addressing within a 16x16 (x4) tile read
    const int g    = lane >> 3;
    const int lr   = lane & 7;
    const int lrow = (g & 1) * 8 + lr;   // row within 16-row tile
    const int lkb  = (g >> 1) * 16;      // 0 or 16 bytes within the 32B k16 slab

    float acc[2][8][4] = {};

    LDG(0); STS(0);
    __syncthreads();

    for (int c = 0; c < NC; ++c) {
        if (c + 1 < NC) LDG(c + 1);
        const uint32_t sb = su + (c & 1) * TC_STAGE;
#pragma unroll
        for (int kk = 0; kk < 4; ++kk) {
            uint32_t ah[2][4], al[2][4];
#pragma unroll
            for (int mt = 0; mt < 2; ++mt) {
                uint32_t off = sw128((uint32_t)((m0 + mt*16 + lrow) * 128 + kk*32 + lkb));
                ldsm4(sb + off,         ah[mt]);
                ldsm4(sb + 16384 + off, al[mt]);
            }
#pragma unroll
            for (int np = 0; np < 4; ++np) {
                uint32_t boff = sw128((uint32_t)((n0 + np*16 + lrow) * 128 + kk*32 + lkb));
                uint32_t bh[4], bl[4];
                ldsm4(sb + 32768 + boff, bh);
                ldsm4(sb + 49152 + boff, bl);
#pragma unroll
                for (int mt = 0; mt < 2; ++mt) {
                    mma_bf16(acc[mt][2*np],   ah[mt], bh[0], bh[2]);
                    mma_bf16(acc[mt][2*np],   ah[mt], bl[0], bl[2]);
                    mma_bf16(acc[mt][2*np],   al[mt], bh[0], bh[2]);
                    mma_bf16(acc[mt][2*np+1], ah[mt], bh[1], bh[3]);
                    mma_bf16(acc[mt][2*np+1], ah[mt], bl[1], bl[3]);
                    mma_bf16(acc[mt][2*np+1], al[mt], bh[1], bh[3]);
                }
            }
        }
        if (c + 1 < NC) STS((c + 1) & 1);
        __syncthreads();
    }

    // epilogue: c fragment (m = lane>>2 (+8), n = (lane&3)*2)
    const int er = lane >> 2;
    const int ec = (lane & 3) * 2;
#pragma unroll
    for (int mt = 0; mt < 2; ++mt) {
#pragma unroll
        for (int nt = 0; nt < 8; ++nt) {
            const int row = bm + m0 + mt*16 + er;
            const int col = bn + n0 + nt*8 + ec;
            float2 lo = { acc[mt][nt][0], acc[mt][nt][1] };
            float2 hi = { acc[mt][nt][2], acc[mt][nt][3] };
            *(float2*)(C + (size_t)row * N + col)       = lo;
            *(float2*)(C + (size_t)(row + 8) * N + col) = hi;
        }
    }
}

// ---------------------------------------------------------------------------
// Depthwise causal conv (K=4) + bias + SiLU, with transpose to (b, t, d).
// ---------------------------------------------------------------------------
__global__ void __launch_bounds__(256) conv_silu_kernel(
    const float* __restrict__ cw_f, const float* __restrict__ cb_f,
    const float* __restrict__ cw_b, const float* __restrict__ cb_b)
{
    const int t0 = blockIdx.x * 128;
    const int d0 = blockIdx.y * 32;
    const int b   = blockIdx.z & 1;
    const int dir = blockIdx.z >> 1;

    __shared__ float xs[32][133];

    const float* xbase = g_xz + ((size_t)b * (2*CDI) + d0) * CL;
    const int base = (dir == 0) ? (t0 - 3) : (CL - 128 - t0);

    const int lane = threadIdx.x & 31;
    const int wy   = threadIdx.x >> 5;
    for (int d = wy; d < 32; d += 8) {
        const float* row = xbase + (size_t)d * CL;
        for (int i = lane; i < 131; i += 32) {
            int u = base + i;
            xs[d][i] = (u >= 0 && u < CL) ? row[u] : 0.f;
        }
    }
    __syncthreads();

    const int d  = threadIdx.x & 31;
    const int sg = threadIdx.x >> 5;
    const float* cw = dir ? cw_b : cw_f;
    const float* cb = dir ? cb_b : cb_f;
    const float w0 = cw[(d0+d)*CK + 0];
    const float w1 = cw[(d0+d)*CK + 1];
    const float w2 = cw[(d0+d)*CK + 2];
    const float w3 = cw[(d0+d)*CK + 3];
    const float bias = cb[d0+d];

    float* out = g_xt[dir] + (size_t)b * CL * CDI;
#pragma unroll
    for (int q = 0; q < 16; ++q) {
        int s = sg + 8*q;
        float v;
        if (dir == 0) {
            v = w0*xs[d][s] + w1*xs[d][s+1] + w2*xs[d][s+2] + w3*xs[d][s+3] + bias;
        } else {
            v = w3*xs[d][127-s] + w2*xs[d][127-s+1] + w1*xs[d][127-s+2] + w0*xs[d][127-s+3] + bias;
        }
        float sv = v / (1.f + __expf(-v));
        out[(size_t)(t0 + s) * CDI + d0 + d] = sv;
    }
}

// ---------------------------------------------------------------------------
// xproj: dbl[row, r] = sum_d xt[row, d] * W[r, d],  rows=B*L, r<80, K=1536
// ---------------------------------------------------------------------------
__global__ void __launch_bounds__(256) xproj_kernel(
    const float* __restrict__ xpw_f, const float* __restrict__ xpw_b)
{
    const int dir = blockIdx.y;
    const float* W = dir ? xpw_b : xpw_f;
    const float* X = g_xt[dir];
    float* O = g_dbl[dir];
    const int r0 = blockIdx.x * 128;

    __shared__ __align__(16) float Xs[16][128];
    __shared__ float Ws[16][80];

    const int tid = threadIdx.x;
    const int tx = tid & 15;
    const int ty = tid >> 4;
    const int xr = tid >> 1;
    const int xk = (tid & 1) * 8;

    float acc[8][5] = {};

    for (int k0 = 0; k0 < CDI; k0 += 16) {
        float4 v0 = *(const float4*)(X + (size_t)(r0+xr)*CDI + k0 + xk);
        float4 v1 = *(const float4*)(X + (size_t)(r0+xr)*CDI + k0 + xk + 4);
        float wv[5];
#pragma unroll
        for (int p = 0; p < 5; ++p) {
            int idx = tid + p*256;
            int wr = idx >> 4, wk = idx & 15;
            wv[p] = W[(size_t)wr*CDI + k0 + wk];
        }
        __syncthreads();
        Xs[xk+0][xr]=v0.x; Xs[xk+1][xr]=v0.y; Xs[xk+2][xr]=v0.z; Xs[xk+3][xr]=v0.w;
        Xs[xk+4][xr]=v1.x; Xs[xk+5][xr]=v1.y; Xs[xk+6][xr]=v1.z; Xs[xk+7][xr]=v1.w;
#pragma unroll
        for (int p = 0; p < 5; ++p) {
            int idx = tid + p*256;
            int wr = idx >> 4, wk = idx & 15;
            Ws[wk][wr] = wv[p];
        }
        __syncthreads();
#pragma unroll
        for (int k = 0; k < 16; ++k) {
            float4 a0 = *(const float4*)&Xs[k][ty*8];
            float4 a1 = *(const float4*)&Xs[k][ty*8+4];
            float a[8] = {a0.x,a0.y,a0.z,a0.w,a1.x,a1.y,a1.z,a1.w};
            float w[5];
#pragma unroll
            for (int j = 0; j < 5; ++j) w[j] = Ws[k][tx*5+j];
#pragma unroll
            for (int i = 0; i < 8; ++i)
#pragma unroll
                for (int j = 0; j < 5; ++j)
                    acc[i][j] = fmaf(a[i], w[j], acc[i][j]);
        }
        __syncthreads();
    }
#pragma unroll
    for (int i = 0; i < 8; ++i)
#pragma unroll
        for (int j = 0; j < 5; ++j)
            O[(size_t)(r0 + ty*8 + i)*CPROJ + tx*5 + j] = acc[i][j];
}

// ---------------------------------------------------------------------------
// dtproj + softplus
// ---------------------------------------------------------------------------
__device__ __forceinline__ float softplus_f(float v) {
    return (v > 20.f) ? v : log1pf(__expf(v));
}

__global__ void __launch_bounds__(256) dtproj_kernel(
    const float* __restrict__ dtw_f, const float* __restrict__ dtb_f,
    const float* __restrict__ dtw_b, const float* __restrict__ dtb_b)
{
    const int dir = blockIdx.z;
    const float* W    = dir ? dtw_b : dtw_f;
    const float* bias = dir ? dtb_b : dtb_f;
    const float* DT = g_dbl[dir];
    float* O = g_delta[dir];

    const int r0 = blockIdx.x * 64;
    const int d0 = blockIdx.y * 128;

    __shared__ __align__(16) float Ts[48][64];
    __shared__ __align__(16) float Ws2[48][128];

    const int tid = threadIdx.x;
#pragma unroll
    for (int p = 0; p < 3; ++p) {
        int q = tid + p*256;
        int rr = q / 12, kk = (q % 12) * 4;
        float4 v = *(const float4*)(DT + (size_t)(r0+rr)*CPROJ + kk);
        Ts[kk+0][rr]=v.x; Ts[kk+1][rr]=v.y; Ts[kk+2][rr]=v.z; Ts[kk+3][rr]=v.w;
    }
#pragma unroll
    for (int p = 0; p < 6; ++p) {
        int q = tid + p*256;
        int dd = q / 12, kk = (q % 12) * 4;
        float4 v = *(const float4*)(W + (size_t)(d0+dd)*CR + kk);
        Ws2[kk+0][dd]=v.x; Ws2[kk+1][dd]=v.y; Ws2[kk+2][dd]=v.z; Ws2[kk+3][dd]=v.w;
    }
    __syncthreads();

    const int tx = tid & 31;
    const int ty = tid >> 5;
    float acc[8][4] = {};
#pragma unroll
    for (int k = 0; k < 48; ++k) {
        float4 a0 = *(const float4*)&Ts[k][ty*8];
        float4 a1 = *(const float4*)&Ts[k][ty*8+4];
        float a[8] = {a0.x,a0.y,a0.z,a0.w,a1.x,a1.y,a1.z,a1.w};
        float4 w = *(const float4*)&Ws2[k][tx*4];
        float ww[4] = {w.x, w.y, w.z, w.w};
#pragma unroll
        for (int i = 0; i < 8; ++i)
#pragma unroll
            for (int j = 0; j < 4; ++j)
                acc[i][j] = fmaf(a[i], ww[j], acc[i][j]);
    }

    const int tx4 = tx*4;
    float b0 = bias[d0+tx4+0], b1 = bias[d0+tx4+1], b2 = bias[d0+tx4+2], b3 = bias[d0+tx4+3];
#pragma unroll
    for (int i = 0; i < 8; ++i) {
        float4 v;
        v.x = softplus_f(acc[i][0] + b0);
        v.y = softplus_f(acc[i][1] + b1);
        v.z = softplus_f(acc[i][2] + b2);
        v.w = softplus_f(acc[i][3] + b3);
        *(float4*)(O + (size_t)(r0 + ty*8 + i)*CDI + d0 + tx4) = v;
    }
}

// ---------------------------------------------------------------------------
// Selective scan (warp = 2 channels x 16 states)
// ---------------------------------------------------------------------------
__global__ void __launch_bounds__(256) scan_kernel(
    const float* __restrict__ Alog_f, const float* __restrict__ Dv_f,
    const float* __restrict__ Alog_b, const float* __restrict__ Dv_b)
{
    const int dir = blockIdx.z;
    const int b   = blockIdx.y;
    const int d0  = blockIdx.x * 16;

    const float* Alog = dir ? Alog_b : Alog_f;
    const float* Dvec = dir ? Dv_b   : Dv_f;
    const float* delta = g_delta[dir] + (size_t)b * CL * CDI;
    const float* xt    = g_xt[dir]    + (size_t)b * CL * CDI;
    const float* dbl   = g_dbl[dir]   + (size_t)b * CL * CPROJ;
    float* yout        = g_y[dir]     + (size_t)b * CL * CDI;

    __shared__ __align__(16) float sd[64][16];
    __shared__ __align__(16) float sx[64][16];
    __shared__ __align__(16) float sB[64][16];
    __shared__ __align__(16) float sC[64][16];

    const int tid  = threadIdx.x;
    const int lane = tid & 31;
    const int wid  = tid >> 5;
    const int half = lane >> 4;
    const int n    = lane & 15;
    const int ch   = wid*2 + half;
    const int d    = d0 + ch;

    const float Aval = -__expf(Alog[d*CN + n]);
    const float Dval = Dvec[d];
    float h = 0.f;

    const int li = tid >> 2;
    const int lj = (tid & 3) * 4;

    float4 rd, rx, rB, rC;
    auto LD = [&](int t0) {
        rd = *(const float4*)(delta + (size_t)(t0+li)*CDI + d0 + lj);
        rx = *(const float4*)(xt    + (size_t)(t0+li)*CDI + d0 + lj);
        rB = *(const float4*)(dbl + (size_t)(t0+li)*CPROJ + CR + lj);
        rC = *(const float4*)(dbl + (size_t)(t0+li)*CPROJ + CR + CN + lj);
    };
    LD(0);

    const int NCH = CL / 64;
    for (int c = 0; c < NCH; ++c) {
        __syncthreads();
        *(float4*)&sd[li][lj] = rd;
        *(float4*)&sx[li][lj] = rx;
        *(float4*)&sB[li][lj] = rB;
        *(float4*)&sC[li][lj] = rC;
        __syncthreads();
        if (c + 1 < NCH) LD((c+1) * 64);

        const int tbase = c * 64;
#pragma unroll 8
        for (int s = 0; s < 64; ++s) {
            float dt = sd[s][ch];
            float xv = sx[s][ch];
            float Bv = sB[s][n];
            float Cv = sC[s][n];
            float a = __expf(dt * Aval);
            h = fmaf(a, h, dt * xv * Bv);
            float p = h * Cv;
            p += __shfl_xor_sync(0xffffffffu, p, 8);
            p += __shfl_xor_sync(0xffffffffu, p, 4);
            p += __shfl_xor_sync(0xffffffffu, p, 2);
            p += __shfl_xor_sync(0xffffffffu, p, 1);
            if (n == 0)
                yout[(size_t)(tbase + s)*CDI + d] = p + xv * Dval;
        }
    }
}

// ---------------------------------------------------------------------------
// Gate + direction merge
// ---------------------------------------------------------------------------
__global__ void __launch_bounds__(256) combine_kernel()
{
    const int l0 = blockIdx.x * 32;
    const int d0 = blockIdx.y * 32;
    const int b  = blockIdx.z;

    __shared__ float zs[32][33];
    const int lane = threadIdx.x & 31;
    const int wy   = threadIdx.x >> 5;

    const float* zbase = g_xz + ((size_t)b * (2*CDI) + CDI + d0) * CL;
    for (int dd = wy; dd < 32; dd += 8)
        zs[dd][lane] = zbase[(size_t)dd * CL + l0 + lane];
    __syncthreads();

#pragma unroll
    for (int q = 0; q < 4; ++q) {
        int lr = wy + 8*q;
        int l = l0 + lr;
        size_t idx  = ((size_t)b*CL + l)*CDI + d0 + lane;
        size_t idxr = ((size_t)b*CL + (CL-1-l))*CDI + d0 + lane;
        float yf = g_y[0][idx];
        float yb = g_y[1][idxr];
        float zv = zs[lane][lr];
        float s = zv / (1.f + __expf(-zv));
        g_comb[idx] = (yf + yb) * s;
    }
}

// ---------------------------------------------------------------------------
// Launcher
// ---------------------------------------------------------------------------
extern "C" void kernel_launch(void* const* d_in, const int* in_sizes, int n_in,
                              void* d_out, int out_size)
{
    (void)in_sizes; (void)n_in; (void)out_size;

    const float* hidden  = (const float*)d_in[0];
    const float* in_w    = (const float*)d_in[1];
    const float* conv_w  = (const float*)d_in[2];
    const float* conv_b  = (const float*)d_in[3];
    const float* xproj_w = (const float*)d_in[4];
    const float* dtw     = (const float*)d_in[5];
    const float* dtb     = (const float*)d_in[6];
    const float* A_log   = (const float*)d_in[7];
    const float* Dv      = (const float*)d_in[8];
    const float* conv_w2 = (const float*)d_in[9];
    const float* conv_b2 = (const float*)d_in[10];
    const float* xproj_w2= (const float*)d_in[11];
    const float* dtw2    = (const float*)d_in[12];
    const float* dtb2    = (const float*)d_in[13];
    const float* A_log2  = (const float*)d_in[14];
    const float* Dv2     = (const float*)d_in[15];
    const float* out_w   = (const float*)d_in[16];

    void* p_xz = nullptr;
    void* p_comb = nullptr;
    cudaGetSymbolAddress(&p_xz, g_xz);
    cudaGetSymbolAddress(&p_comb, g_comb);

    cudaFuncSetAttribute(gemm_tc_kernel,
                         cudaFuncAttributeMaxDynamicSharedMemorySize, TC_SMEM);

    // 1) in_proj: xz[b,e,l] = sum_d W[e,d] * hidden[b,l,d]
    //    A = in_w (3072 x 768), B = hidden rows (4096 x 768), C stride (b).
    gemm_tc_kernel<<<dim3(CL/128, (2*CDI)/128, CB), 256, TC_SMEM>>>(
        in_w, hidden, (float*)p_xz, CL, CDM,
        (long long)CL * CDM, (long long)(2*CDI) * CL, CDM / 64);

    // 2) conv + SiLU + transpose
    conv_silu_kernel<<<dim3(CL/128, CDI/32, 2*CB), 256>>>(
        conv_w, conv_b, conv_w2, conv_b2);

    // 3) xproj -> dbl (dt|B|C)
    xproj_kernel<<<dim3((CB*CL)/128, 2), 256>>>(xproj_w, xproj_w2);

    // 4) dtproj + softplus -> delta
    dtproj_kernel<<<dim3((CB*CL)/64, CDI/128, 2), 256>>>(dtw, dtb, dtw2, dtb2);

    // 5) selective scan
    scan_kernel<<<dim3(CDI/16, CB, 2), 256>>>(A_log, Dv, A_log2, Dv2);

    // 6) gate + direction merge
    combine_kernel<<<dim3(CL/32, CDI/32, CB), 256>>>();

    // 7) out_proj: A = comb (8192 x 1536), B = out_w (768 x 1536).
    gemm_tc_kernel<<<dim3(CDM/128, (CB*CL)/128, 1), 256, TC_SMEM>>>(
        (const float*)p_comb, out_w, (float*)d_out, CDM, CDI,
        0, 0, CDI / 64);
}

// round 4
// speedup vs baseline: 1.6582x; 1.1508x over previous
#include <cuda_runtime.h>
#include <cuda_bf16.h>
#include <cstdint>

// Problem constants
constexpr int CB  = 2;     // batch
constexpr int CL  = 4096;  // seq len
constexpr int CDM = 768;   // d_model
constexpr int CDI = 1536;  // d_inner
constexpr int CN  = 16;    // state dim
constexpr int CR  = 48;    // dt rank
constexpr int CK  = 4;     // conv width
constexpr int CPROJ = CR + 2*CN; // 80

// ---------------------------------------------------------------------------
// Scratch (device globals; no runtime allocation allowed)
// ---------------------------------------------------------------------------
__device__ float g_xz[CB * 2 * CDI * CL];        // (b, e, l)
__device__ float g_xt[2][CB * CL * CDI];         // per dir, (b, t, d)
__device__ float g_dbl[2][CB * CL * CPROJ];      // per dir, (b*L, 80): dt|B|C
__device__ float g_delta[2][CB * CL * CDI];      // per dir, post-softplus
__device__ float g_y[2][CB * CL * CDI];          // per dir, scan out (+D*x)

// bf16 hi/lo packed operands for tensor GEMMs
__device__ __nv_bfloat16 g_hid_h[CB*CL*CDM],  g_hid_l[CB*CL*CDM];
__device__ __nv_bfloat16 g_w1_h[2*CDI*CDM],   g_w1_l[2*CDI*CDM];
__device__ __nv_bfloat16 g_w2_h[CDM*CDI],     g_w2_l[CDM*CDI];
__device__ __nv_bfloat16 g_wx_h[2][128*CDI],  g_wx_l[2][128*CDI];   // xproj W padded 80->128 rows
__device__ __nv_bfloat16 g_xth[2][CB*CL*CDI], g_xtl[2][CB*CL*CDI];
__device__ __nv_bfloat16 g_cmb_h[CB*CL*CDI],  g_cmb_l[CB*CL*CDI];

// ---------------------------------------------------------------------------
// PTX helpers
// ---------------------------------------------------------------------------
__device__ __forceinline__ uint32_t smem_u32(const void* p) {
    uint32_t a;
    asm("{ .reg .u64 t; cvta.to.shared.u64 t, %1; cvt.u32.u64 %0, t; }" : "=r"(a) : "l"(p));
    return a;
}
__device__ __forceinline__ uint32_t sw128(uint32_t b) { return b ^ ((b >> 3) & 0x70); }

__device__ __forceinline__ void ldsm4(uint32_t addr, uint32_t r[4]) {
    asm volatile("ldmatrix.sync.aligned.m8n8.x4.shared.b16 {%0,%1,%2,%3}, [%4];"
        : "=r"(r[0]), "=r"(r[1]), "=r"(r[2]), "=r"(r[3]) : "r"(addr));
}
__device__ __forceinline__ void mma_bf16(float* d, const uint32_t* a, uint32_t b0, uint32_t b1) {
    asm volatile("mma.sync.aligned.m16n8k16.row.col.f32.bf16.bf16.f32 "
        "{%0,%1,%2,%3}, {%4,%5,%6,%7}, {%8,%9}, {%0,%1,%2,%3};"
        : "+f"(d[0]), "+f"(d[1]), "+f"(d[2]), "+f"(d[3])
        : "r"(a[0]), "r"(a[1]), "r"(a[2]), "r"(a[3]), "r"(b0), "r"(b1));
}
__device__ __forceinline__ void cp16(uint32_t s, const void* g) {
    asm volatile("cp.async.ca.shared.global [%0], [%1], 16;" :: "r"(s), "l"(g));
}

// ---------------------------------------------------------------------------
// Pure-bf16 tensor GEMM:  C[m,n] = sum_k A[m,k]*B[n,k]  (3-term hi/lo split)
// Operands prepacked as bf16 hi/lo row-major [*,Kd]. CTA tile 128x128, BK=64.
// 3-stage cp.async ring; mainloop = cp.async + ldmatrix + mma only.
// Stage (64KB): Ah 16K | Al 16K | Bh 16K | Bl 16K.  Epilogue col-guard Nout.
// ---------------------------------------------------------------------------
constexpr int GB_STAGE = 65536;
constexpr int GB_SMEM  = 3 * GB_STAGE;   // 196608 B

__global__ void __launch_bounds__(256) gemm_bf16_kernel(
    const __nv_bfloat16* __restrict__ Ah, const __nv_bfloat16* __restrict__ Al,
    const __nv_bfloat16* __restrict__ Bh, const __nv_bfloat16* __restrict__ Bl,
    float* __restrict__ C, int Nout, int Kd,
    long long strideA, long long strideB, long long strideC, int NC)
{
    extern __shared__ __align__(1024) char smem[];
    const uint32_t su = smem_u32(smem);
    Ah += (size_t)blockIdx.z * strideA;
    Al += (size_t)blockIdx.z * strideA;
    Bh += (size_t)blockIdx.z * strideB;
    Bl += (size_t)blockIdx.z * strideB;
    C  += (size_t)blockIdx.z * strideC;
    const int bm = blockIdx.y * 128;
    const int bn = blockIdx.x * 128;
    const int tid  = threadIdx.x;
    const int wid  = tid >> 5;
    const int lane = tid & 31;

    // producer: one 128x64 bf16 tile per array per chunk (cp.async 16B x4/thread/array)
    const int prow = tid >> 3;          // 0..31 -> x4 gives 128 rows
    const int pkc  = tid & 7;           // 16B chunk within 128B row
    auto issue = [&](int c) {
        const uint32_t sb = su + (uint32_t)(c % 3) * GB_STAGE;
        const int k0 = c * 64;
#pragma unroll
        for (int i = 0; i < 4; ++i) {
            const int row = prow + i * 32;
            const uint32_t off = sw128((uint32_t)(row * 128 + pkc * 16));
            const size_t ga = (size_t)(bm + row) * Kd + k0 + pkc * 8;
            const size_t gb = (size_t)(bn + row) * Kd + k0 + pkc * 8;
            cp16(sb + off,         Ah + ga);
            cp16(sb + 16384 + off, Al + ga);
            cp16(sb + 32768 + off, Bh + gb);
            cp16(sb + 49152 + off, Bl + gb);
        }
        asm volatile("cp.async.commit_group;" ::: "memory");
    };

    // warp tiling: 4x2 warps, warp tile 32 (m) x 64 (n)
    const int m0 = (wid & 3) * 32;
    const int n0 = (wid >> 2) * 64;
    const int g    = lane >> 3;
    const int lr   = lane & 7;
    const int lrow = (g & 1) * 8 + lr;
    const int lkb  = (g >> 1) * 16;

    float acc[2][8][4] = {};

    issue(0); issue(1); issue(2);      // NC >= 3 always here

    for (int c = 0; c < NC; ++c) {
        asm volatile("cp.async.wait_group 2;" ::: "memory");
        __syncthreads();
        const uint32_t sb = su + (uint32_t)(c % 3) * GB_STAGE;
#pragma unroll
        for (int kk = 0; kk < 4; ++kk) {
            uint32_t ah[2][4], al[2][4];
#pragma unroll
            for (int mt = 0; mt < 2; ++mt) {
                uint32_t off = sw128((uint32_t)((m0 + mt*16 + lrow) * 128 + kk*32 + lkb));
                ldsm4(sb + off,         ah[mt]);
                ldsm4(sb + 16384 + off, al[mt]);
            }
#pragma unroll
            for (int np = 0; np < 4; ++np) {
                uint32_t boff = sw128((uint32_t)((n0 + np*16 + lrow) * 128 + kk*32 + lkb));
                uint32_t bh[4], bl[4];
                ldsm4(sb + 32768 + boff, bh);
                ldsm4(sb + 49152 + boff, bl);
#pragma unroll
                for (int mt = 0; mt < 2; ++mt) {
                    mma_bf16(acc[mt][2*np],   ah[mt], bh[0], bh[2]);
                    mma_bf16(acc[mt][2*np],   ah[mt], bl[0], bl[2]);
                    mma_bf16(acc[mt][2*np],   al[mt], bh[0], bh[2]);
                    mma_bf16(acc[mt][2*np+1], ah[mt], bh[1], bh[3]);
                    mma_bf16(acc[mt][2*np+1], ah[mt], bl[1], bl[3]);
                    mma_bf16(acc[mt][2*np+1], al[mt], bh[1], bh[3]);
                }
            }
        }
        __syncthreads();
        if (c + 3 < NC) issue(c + 3);
        else asm volatile("cp.async.commit_group;" ::: "memory");  // keep group count uniform
    }

    // epilogue
    const int er = lane >> 2;
    const int ec = (lane & 3) * 2;
#pragma unroll
    for (int mt = 0; mt < 2; ++mt) {
#pragma unroll
        for (int nt = 0; nt < 8; ++nt) {
            const int row = bm + m0 + mt*16 + er;
            const int col = bn + n0 + nt*8 + ec;
            if (col < Nout) {
                float2 lo = { acc[mt][nt][0], acc[mt][nt][1] };
                float2 hi = { acc[mt][nt][2], acc[mt][nt][3] };
                *(float2*)(C + (size_t)row * Nout + col)       = lo;
                *(float2*)(C + (size_t)(row + 8) * Nout + col) = hi;
            }
        }
    }
}

// ---------------------------------------------------------------------------
// fp32 -> bf16 hi/lo splitter (grid-stride, float4)
// ---------------------------------------------------------------------------
__global__ void split_kernel(const float* __restrict__ s,
                             __nv_bfloat16* __restrict__ h,
                             __nv_bfloat16* __restrict__ l, int n4)
{
    for (int i = blockIdx.x * blockDim.x + threadIdx.x; i < n4;
         i += gridDim.x * blockDim.x) {
        float4 v = ((const float4*)s)[i];
        __nv_bfloat162 h01 = __floats2bfloat162_rn(v.x, v.y);
        __nv_bfloat162 h23 = __floats2bfloat162_rn(v.z, v.w);
        __nv_bfloat162 l01 = __floats2bfloat162_rn(v.x - __bfloat162float(h01.x),
                                                   v.y - __bfloat162float(h01.y));
        __nv_bfloat162 l23 = __floats2bfloat162_rn(v.z - __bfloat162float(h23.x),
                                                   v.w - __bfloat162float(h23.y));
        ((uint2*)h)[i] = make_uint2(*(uint32_t*)&h01, *(uint32_t*)&h23);
        ((uint2*)l)[i] = make_uint2(*(uint32_t*)&l01, *(uint32_t*)&l23);
    }
}

// xproj weights: pad 80 -> 128 rows (zeros), split to bf16 hi/lo, both dirs.
__global__ void padw_kernel(const float* __restrict__ wf, const float* __restrict__ wb)
{
    const int total4 = 2 * 128 * CDI / 4;
    for (int i = blockIdx.x * blockDim.x + threadIdx.x; i < total4;
         i += gridDim.x * blockDim.x) {
        int e = i * 4;
        int dir = e / (128 * CDI);
        int rem = e - dir * 128 * CDI;
        int row = rem / CDI;
        int k   = rem - row * CDI;
        float4 v = {0.f, 0.f, 0.f, 0.f};
        const float* W = dir ? wb : wf;
        if (row < CPROJ) v = *(const float4*)(W + (size_t)row * CDI + k);
        __nv_bfloat162 h01 = __floats2bfloat162_rn(v.x, v.y);
        __nv_bfloat162 h23 = __floats2bfloat162_rn(v.z, v.w);
        __nv_bfloat162 l01 = __floats2bfloat162_rn(v.x - __bfloat162float(h01.x),
                                                   v.y - __bfloat162float(h01.y));
        __nv_bfloat162 l23 = __floats2bfloat162_rn(v.z - __bfloat162float(h23.x),
                                                   v.w - __bfloat162float(h23.y));
        ((uint2*)&g_wx_h[0][0])[i] = make_uint2(*(uint32_t*)&h01, *(uint32_t*)&h23);
        ((uint2*)&g_wx_l[0][0])[i] = make_uint2(*(uint32_t*)&l01, *(uint32_t*)&l23);
    }
}

// ---------------------------------------------------------------------------
// Depthwise causal conv (K=4) + bias + SiLU, transpose to (b,t,d).
// Emits fp32 xt (scan) + bf16 hi/lo xt (xproj GEMM operand).
// ---------------------------------------------------------------------------
__global__ void __launch_bounds__(256) conv_silu_kernel(
    const float* __restrict__ cw_f, const float* __restrict__ cb_f,
    const float* __restrict__ cw_b, const float* __restrict__ cb_b)
{
    const int t0 = blockIdx.x * 128;
    const int d0 = blockIdx.y * 32;
    const int b   = blockIdx.z & 1;
    const int dir = blockIdx.z >> 1;

    __shared__ float xs[32][133];

    const float* xbase = g_xz + ((size_t)b * (2*CDI) + d0) * CL;
    const int base = (dir == 0) ? (t0 - 3) : (CL - 128 - t0);

    const int lane = threadIdx.x & 31;
    const int wy   = threadIdx.x >> 5;
    for (int d = wy; d < 32; d += 8) {
        const float* row = xbase + (size_t)d * CL;
        for (int i = lane; i < 131; i += 32) {
            int u = base + i;
            xs[d][i] = (u >= 0 && u < CL) ? row[u] : 0.f;
        }
    }
    __syncthreads();

    const int d  = threadIdx.x & 31;
    const int sg = threadIdx.x >> 5;
    const float* cw = dir ? cw_b : cw_f;
    const float* cb = dir ? cb_b : cb_f;
    const float w0 = cw[(d0+d)*CK + 0];
    const float w1 = cw[(d0+d)*CK + 1];
    const float w2 = cw[(d0+d)*CK + 2];
    const float w3 = cw[(d0+d)*CK + 3];
    const float bias = cb[d0+d];

    float* out = g_xt[dir] + (size_t)b * CL * CDI;
    __nv_bfloat16* oh = g_xth[dir] + (size_t)b * CL * CDI;
    __nv_bfloat16* ol = g_xtl[dir] + (size_t)b * CL * CDI;
#pragma unroll
    for (int q = 0; q < 16; ++q) {
        int s = sg + 8*q;
        float v;
        if (dir == 0) {
            v = w0*xs[d][s] + w1*xs[d][s+1] + w2*xs[d][s+2] + w3*xs[d][s+3] + bias;
        } else {
            v = w3*xs[d][127-s] + w2*xs[d][127-s+1] + w1*xs[d][127-s+2] + w0*xs[d][127-s+3] + bias;
        }
        float sv = v / (1.f + __expf(-v));
        size_t idx = (size_t)(t0 + s) * CDI + d0 + d;
        out[idx] = sv;
        __nv_bfloat16 hb = __float2bfloat16(sv);
        oh[idx] = hb;
        ol[idx] = __float2bfloat16(sv - __bfloat162float(hb));
    }
}

// ---------------------------------------------------------------------------
// dtproj + softplus (SIMT; round-5 target)
// ---------------------------------------------------------------------------
__device__ __forceinline__ float softplus_f(float v) {
    return (v > 20.f) ? v : log1pf(__expf(v));
}

__global__ void __launch_bounds__(256) dtproj_kernel(
    const float* __restrict__ dtw_f, const float* __restrict__ dtb_f,
    const float* __restrict__ dtw_b, const float* __restrict__ dtb_b)
{
    const int dir = blockIdx.z;
    const float* W    = dir ? dtw_b : dtw_f;
    const float* bias = dir ? dtb_b : dtb_f;
    const float* DT = g_dbl[dir];
    float* O = g_delta[dir];

    const int r0 = blockIdx.x * 64;
    const int d0 = blockIdx.y * 128;

    __shared__ __align__(16) float Ts[48][64];
    __shared__ __align__(16) float Ws2[48][128];

    const int tid = threadIdx.x;
#pragma unroll
    for (int p = 0; p < 3; ++p) {
        int q = tid + p*256;
        int rr = q / 12, kk = (q % 12) * 4;
        float4 v = *(const float4*)(DT + (size_t)(r0+rr)*CPROJ + kk);
        Ts[kk+0][rr]=v.x; Ts[kk+1][rr]=v.y; Ts[kk+2][rr]=v.z; Ts[kk+3][rr]=v.w;
    }
#pragma unroll
    for (int p = 0; p < 6; ++p) {
        int q = tid + p*256;
        int dd = q / 12, kk = (q % 12) * 4;
        float4 v = *(const float4*)(W + (size_t)(d0+dd)*CR + kk);
        Ws2[kk+0][dd]=v.x; Ws2[kk+1][dd]=v.y; Ws2[kk+2][dd]=v.z; Ws2[kk+3][dd]=v.w;
    }
    __syncthreads();

    const int tx = tid & 31;
    const int ty = tid >> 5;
    float acc[8][4] = {};
#pragma unroll
    for (int k = 0; k < 48; ++k) {
        float4 a0 = *(const float4*)&Ts[k][ty*8];
        float4 a1 = *(const float4*)&Ts[k][ty*8+4];
        float a[8] = {a0.x,a0.y,a0.z,a0.w,a1.x,a1.y,a1.z,a1.w};
        float4 w = *(const float4*)&Ws2[k][tx*4];
        float ww[4] = {w.x, w.y, w.z, w.w};
#pragma unroll
        for (int i = 0; i < 8; ++i)
#pragma unroll
            for (int j = 0; j < 4; ++j)
                acc[i][j] = fmaf(a[i], ww[j], acc[i][j]);
    }

    const int tx4 = tx*4;
    float b0 = bias[d0+tx4+0], b1 = bias[d0+tx4+1], b2 = bias[d0+tx4+2], b3 = bias[d0+tx4+3];
#pragma unroll
    for (int i = 0; i < 8; ++i) {
        float4 v;
        v.x = softplus_f(acc[i][0] + b0);
        v.y = softplus_f(acc[i][1] + b1);
        v.z = softplus_f(acc[i][2] + b2);
        v.w = softplus_f(acc[i][3] + b3);
        *(float4*)(O + (size_t)(r0 + ty*8 + i)*CDI + d0 + tx4) = v;
    }
}

// ---------------------------------------------------------------------------
// Selective scan (warp = 2 channels x 16 states)
// ---------------------------------------------------------------------------
__global__ void __launch_bounds__(256) scan_kernel(
    const float* __restrict__ Alog_f, const float* __restrict__ Dv_f,
    const float* __restrict__ Alog_b, const float* __restrict__ Dv_b)
{
    const int dir = blockIdx.z;
    const int b   = blockIdx.y;
    const int d0  = blockIdx.x * 16;

    const float* Alog = dir ? Alog_b : Alog_f;
    const float* Dvec = dir ? Dv_b   : Dv_f;
    const float* delta = g_delta[dir] + (size_t)b * CL * CDI;
    const float* xt    = g_xt[dir]    + (size_t)b * CL * CDI;
    const float* dbl   = g_dbl[dir]   + (size_t)b * CL * CPROJ;
    float* yout        = g_y[dir]     + (size_t)b * CL * CDI;

    __shared__ __align__(16) float sd[64][16];
    __shared__ __align__(16) float sx[64][16];
    __shared__ __align__(16) float sB[64][16];
    __shared__ __align__(16) float sC[64][16];

    const int tid  = threadIdx.x;
    const int lane = tid & 31;
    const int wid  = tid >> 5;
    const int half = lane >> 4;
    const int n    = lane & 15;
    const int ch   = wid*2 + half;
    const int d    = d0 + ch;

    const float Aval = -__expf(Alog[d*CN + n]);
    const float Dval = Dvec[d];
    float h = 0.f;

    const int li = tid >> 2;
    const int lj = (tid & 3) * 4;

    float4 rd, rx, rB, rC;
    auto LD = [&](int t0) {
        rd = *(const float4*)(delta + (size_t)(t0+li)*CDI + d0 + lj);
        rx = *(const float4*)(xt    + (size_t)(t0+li)*CDI + d0 + lj);
        rB = *(const float4*)(dbl + (size_t)(t0+li)*CPROJ + CR + lj);
        rC = *(const float4*)(dbl + (size_t)(t0+li)*CPROJ + CR + CN + lj);
    };
    LD(0);

    const int NCH = CL / 64;
    for (int c = 0; c < NCH; ++c) {
        __syncthreads();
        *(float4*)&sd[li][lj] = rd;
        *(float4*)&sx[li][lj] = rx;
        *(float4*)&sB[li][lj] = rB;
        *(float4*)&sC[li][lj] = rC;
        __syncthreads();
        if (c + 1 < NCH) LD((c+1) * 64);

        const int tbase = c * 64;
#pragma unroll 8
        for (int s = 0; s < 64; ++s) {
            float dt = sd[s][ch];
            float xv = sx[s][ch];
            float Bv = sB[s][n];
            float Cv = sC[s][n];
            float a = __expf(dt * Aval);
            h = fmaf(a, h, dt * xv * Bv);
            float p = h * Cv;
            p += __shfl_xor_sync(0xffffffffu, p, 8);
            p += __shfl_xor_sync(0xffffffffu, p, 4);
            p += __shfl_xor_sync(0xffffffffu, p, 2);
            p += __shfl_xor_sync(0xffffffffu, p, 1);
            if (n == 0)
                yout[(size_t)(tbase + s)*CDI + d] = p + xv * Dval;
        }
    }
}

// ---------------------------------------------------------------------------
// Gate + direction merge -> bf16 hi/lo comb (out_proj GEMM operand)
// ---------------------------------------------------------------------------
__global__ void __launch_bounds__(256) combine_kernel()
{
    const int l0 = blockIdx.x * 32;
    const int d0 = blockIdx.y * 32;
    const int b  = blockIdx.z;

    __shared__ float zs[32][33];
    const int lane = threadIdx.x & 31;
    const int wy   = threadIdx.x >> 5;

    const float* zbase = g_xz + ((size_t)b * (2*CDI) + CDI + d0) * CL;
    for (int dd = wy; dd < 32; dd += 8)
        zs[dd][lane] = zbase[(size_t)dd * CL + l0 + lane];
    __syncthreads();

#pragma unroll
    for (int q = 0; q < 4; ++q) {
        int lr = wy + 8*q;
        int l = l0 + lr;
        size_t idx  = ((size_t)b*CL + l)*CDI + d0 + lane;
        size_t idxr = ((size_t)b*CL + (CL-1-l))*CDI + d0 + lane;
        float yf = g_y[0][idx];
        float yb = g_y[1][idxr];
        float zv = zs[lane][lr];
        float s = zv / (1.f + __expf(-zv));
        float cv = (yf + yb) * s;
        __nv_bfloat16 hb = __float2bfloat16(cv);
        g_cmb_h[idx] = hb;
        g_cmb_l[idx] = __float2bfloat16(cv - __bfloat162float(hb));
    }
}

// ---------------------------------------------------------------------------
// Launcher
// ---------------------------------------------------------------------------
extern "C" void kernel_launch(void* const* d_in, const int* in_sizes, int n_in,
                              void* d_out, int out_size)
{
    (void)in_sizes; (void)n_in; (void)out_size;

    const float* hidden  = (const float*)d_in[0];
    const float* in_w    = (const float*)d_in[1];
    const float* conv_w  = (const float*)d_in[2];
    const float* conv_b  = (const float*)d_in[3];
    const float* xproj_w = (const float*)d_in[4];
    const float* dtw     = (const float*)d_in[5];
    const float* dtb     = (const float*)d_in[6];
    const float* A_log   = (const float*)d_in[7];
    const float* Dv      = (const float*)d_in[8];
    const float* conv_w2 = (const float*)d_in[9];
    const float* conv_b2 = (const float*)d_in[10];
    const float* xproj_w2= (const float*)d_in[11];
    const float* dtw2    = (const float*)d_in[12];
    const float* dtb2    = (const float*)d_in[13];
    const float* A_log2  = (const float*)d_in[14];
    const float* Dv2     = (const float*)d_in[15];
    const float* out_w   = (const float*)d_in[16];

    void *p_xz, *p_dbl;
    void *p_hid_h, *p_hid_l, *p_w1_h, *p_w1_l, *p_w2_h, *p_w2_l;
    void *p_wx_h, *p_wx_l, *p_xth, *p_xtl, *p_cmb_h, *p_cmb_l;
    cudaGetSymbolAddress(&p_xz, g_xz);
    cudaGetSymbolAddress(&p_dbl, g_dbl);
    cudaGetSymbolAddress(&p_hid_h, g_hid_h);
    cudaGetSymbolAddress(&p_hid_l, g_hid_l);
    cudaGetSymbolAddress(&p_w1_h, g_w1_h);
    cudaGetSymbolAddress(&p_w1_l, g_w1_l);
    cudaGetSymbolAddress(&p_w2_h, g_w2_h);
    cudaGetSymbolAddress(&p_w2_l, g_w2_l);
    cudaGetSymbolAddress(&p_wx_h, g_wx_h);
    cudaGetSymbolAddress(&p_wx_l, g_wx_l);
    cudaGetSymbolAddress(&p_xth, g_xth);
    cudaGetSymbolAddress(&p_xtl, g_xtl);
    cudaGetSymbolAddress(&p_cmb_h, g_cmb_h);
    cudaGetSymbolAddress(&p_cmb_l, g_cmb_l);

    cudaFuncSetAttribute(gemm_bf16_kernel,
                         cudaFuncAttributeMaxDynamicSharedMemorySize, GB_SMEM);

    // 0) operand packing
    split_kernel<<<1024, 256>>>(hidden, (__nv_bfloat16*)p_hid_h, (__nv_bfloat16*)p_hid_l,
                                CB*CL*CDM/4);
    split_kernel<<<512, 256>>>(in_w, (__nv_bfloat16*)p_w1_h, (__nv_bfloat16*)p_w1_l,
                               2*CDI*CDM/4);
    split_kernel<<<512, 256>>>(out_w, (__nv_bfloat16*)p_w2_h, (__nv_bfloat16*)p_w2_l,
                               CDM*CDI/4);
    padw_kernel<<<512, 256>>>(xproj_w, xproj_w2);

    // 1) in_proj: xz[b,e,l] = W[e,:] . hidden[b,l,:]   M=3072, N=4096, K=768
    gemm_bf16_kernel<<<dim3(CL/128, (2*CDI)/128, CB), 256, GB_SMEM>>>(
        (const __nv_bfloat16*)p_w1_h, (const __nv_bfloat16*)p_w1_l,
        (const __nv_bfloat16*)p_hid_h, (const __nv_bfloat16*)p_hid_l,
        (float*)p_xz, CL, CDM,
        0, (long long)CL * CDM, (long long)(2*CDI) * CL, CDM / 64);

    // 2) conv + SiLU + transpose (+ bf16 hi/lo side output)
    conv_silu_kernel<<<dim3(CL/128, CDI/32, 2*CB), 256>>>(
        conv_w, conv_b, conv_w2, conv_b2);

    // 3) xproj: dbl[row,r] = xt[row,:] . W[r,:]   M=8192 rows, N=80 (pad 128), K=1536
    gemm_bf16_kernel<<<dim3(1, (CB*CL)/128, 2), 256, GB_SMEM>>>(
        (const __nv_bfloat16*)p_xth, (const __nv_bfloat16*)p_xtl,
        (const __nv_bfloat16*)p_wx_h, (const __nv_bfloat16*)p_wx_l,
        (float*)p_dbl, CPROJ, CDI,
        (long long)CB*CL*CDI, (long long)128*CDI, (long long)CB*CL*CPROJ, CDI / 64);

    // 4) dtproj + softplus -> delta
    dtproj_kernel<<<dim3((CB*CL)/64, CDI/128, 2), 256>>>(dtw, dtb, dtw2, dtb2);

    // 5) selective scan
    scan_kernel<<<dim3(CDI/16, CB, 2), 256>>>(A_log, Dv, A_log2, Dv2);

    // 6) gate + direction merge -> bf16 comb
    combine_kernel<<<dim3(CL/32, CDI/32, CB), 256>>>();

    // 7) out_proj: M=8192 rows, N=768, K=1536
    gemm_bf16_kernel<<<dim3(CDM/128, (CB*CL)/128, 1), 256, GB_SMEM>>>(
        (const __nv_bfloat16*)p_cmb_h, (const __nv_bfloat16*)p_cmb_l,
        (const __nv_bfloat16*)p_w2_h, (const __nv_bfloat16*)p_w2_l,
        (float*)d_out, CDM, CDI,
        0, 0, 0, CDI / 64);
}

// round 5
// speedup vs baseline: 1.8561x; 1.1193x over previous
#include <cuda_runtime.h>
#include <cuda_fp16.h>
#include <cstdint>

// Problem constants
constexpr int CB  = 2;     // batch
constexpr int CL  = 4096;  // seq len
constexpr int CDM = 768;   // d_model
constexpr int CDI = 1536;  // d_inner
constexpr int CN  = 16;    // state dim
constexpr int CR  = 48;    // dt rank
constexpr int CK  = 4;     // conv width
constexpr int CPROJ = CR + 2*CN; // 80

// ---------------------------------------------------------------------------
// Scratch (device globals; no runtime allocation allowed)
// ---------------------------------------------------------------------------
__device__ float g_xz[CB * 2 * CDI * CL];        // (b, e, l)
__device__ float g_dbl[2][CB * CL * CPROJ];      // per dir, (b*L, 80): dt|B|C
__device__ float g_delta[2][CB * CL * CDI];      // per dir, post-softplus
__device__ float g_y[2][CB * CL * CDI];          // per dir, scan out (+D*x)

// fp16 operands for tensor GEMMs
__device__ __half g_hid_h[CB*CL*CDM], g_hid_l[CB*CL*CDM];  // hidden hi/lo (split side)
__device__ __half g_w1[2*CDI*CDM];                          // in_proj W (single)
__device__ __half g_w2[CDM*CDI];                            // out_proj W (single)
__device__ __half g_wx[2][128*CDI];                         // xproj W padded 80->128 (single)
__device__ __half g_xth[2][CB*CL*CDI], g_xtl[2][CB*CL*CDI]; // conv out hi/lo (split side)
__device__ __half g_cmb_h[CB*CL*CDI],  g_cmb_l[CB*CL*CDI];  // gated sum hi/lo (split side)

// ---------------------------------------------------------------------------
// PTX helpers
// ---------------------------------------------------------------------------
__device__ __forceinline__ uint32_t smem_u32(const void* p) {
    uint32_t a;
    asm("{ .reg .u64 t; cvta.to.shared.u64 t, %1; cvt.u32.u64 %0, t; }" : "=r"(a) : "l"(p));
    return a;
}
__device__ __forceinline__ uint32_t sw128(uint32_t b) { return b ^ ((b >> 3) & 0x70); }

__device__ __forceinline__ void ldsm4(uint32_t addr, uint32_t r[4]) {
    asm volatile("ldmatrix.sync.aligned.m8n8.x4.shared.b16 {%0,%1,%2,%3}, [%4];"
        : "=r"(r[0]), "=r"(r[1]), "=r"(r[2]), "=r"(r[3]) : "r"(addr));
}
__device__ __forceinline__ void mma_f16(float* d, const uint32_t* a, uint32_t b0, uint32_t b1) {
    asm volatile("mma.sync.aligned.m16n8k16.row.col.f32.f16.f16.f32 "
        "{%0,%1,%2,%3}, {%4,%5,%6,%7}, {%8,%9}, {%0,%1,%2,%3};"
        : "+f"(d[0]), "+f"(d[1]), "+f"(d[2]), "+f"(d[3])
        : "r"(a[0]), "r"(a[1]), "r"(a[2]), "r"(a[3]), "r"(b0), "r"(b1));
}
__device__ __forceinline__ void cp16(uint32_t s, const void* g) {
    asm volatile("cp.async.ca.shared.global [%0], [%1], 16;" :: "r"(s), "l"(g));
}

// ---------------------------------------------------------------------------
// 2-term fp16 tensor GEMM:  C[m,n] = sum_k A[m,k]*B[n,k]  (fp32 out)
// Exactly one operand side is split (hi+lo fp16); the other is single fp16.
// CTA tile 128x128, BK=64, 2-stage cp.async ring, 96KB smem -> 2 CTA/SM.
// Stage (48KB): A-hi 16K | split-lo 16K | B-hi 16K.
// ---------------------------------------------------------------------------
constexpr int GF_STAGE = 49152;
constexpr int GF_SMEM  = 2 * GF_STAGE;   // 98304 B

template <int SPLIT_A>
__global__ void __launch_bounds__(256, 2) gemm_f16_kernel(
    const __half* __restrict__ Ah, const __half* __restrict__ Xl,  // Xl = Al or Bl
    const __half* __restrict__ Bh,
    float* __restrict__ C, int Nout, int Kd,
    long long strideA, long long strideB, long long strideC, int NC)
{
    extern __shared__ __align__(1024) char smem[];
    const uint32_t su = smem_u32(smem);
    Ah += (size_t)blockIdx.z * strideA;
    Bh += (size_t)blockIdx.z * strideB;
    Xl += (size_t)blockIdx.z * (SPLIT_A ? strideA : strideB);
    C  += (size_t)blockIdx.z * strideC;
    const int bm = blockIdx.y * 128;
    const int bn = blockIdx.x * 128;
    const int tid  = threadIdx.x;
    const int wid  = tid >> 5;
    const int lane = tid & 31;

    const int prow = tid >> 3;          // 0..31 -> x4 gives 128 rows
    const int pkc  = tid & 7;           // 16B chunk within 128B row
    auto issue = [&](int c) {
        const uint32_t sb = su + (uint32_t)(c & 1) * GF_STAGE;
        const int k0 = c * 64;
#pragma unroll
        for (int i = 0; i < 4; ++i) {
            const int row = prow + i * 32;
            const uint32_t off = sw128((uint32_t)(row * 128 + pkc * 16));
            const size_t ga = (size_t)(bm + row) * Kd + k0 + pkc * 8;
            const size_t gb = (size_t)(bn + row) * Kd + k0 + pkc * 8;
            cp16(sb + off,         Ah + ga);
            cp16(sb + 16384 + off, Xl + (SPLIT_A ? ga : gb));
            cp16(sb + 32768 + off, Bh + gb);
        }
        asm volatile("cp.async.commit_group;" ::: "memory");
    };

    // warp tiling: 4x2 warps, warp tile 32 (m) x 64 (n)
    const int m0 = (wid & 3) * 32;
    const int n0 = (wid >> 2) * 64;
    const int g    = lane >> 3;
    const int lr   = lane & 7;
    const int lrow = (g & 1) * 8 + lr;
    const int lkb  = (g >> 1) * 16;

    float acc[2][8][4] = {};

    issue(0); issue(1);

    for (int c = 0; c < NC; ++c) {
        asm volatile("cp.async.wait_group 1;" ::: "memory");
        __syncthreads();
        const uint32_t sb = su + (uint32_t)(c & 1) * GF_STAGE;
#pragma unroll
        for (int kk = 0; kk < 4; ++kk) {
            uint32_t ah[2][4], al[2][4];
#pragma unroll
            for (int mt = 0; mt < 2; ++mt) {
                uint32_t off = sw128((uint32_t)((m0 + mt*16 + lrow) * 128 + kk*32 + lkb));
                ldsm4(sb + off, ah[mt]);
                if (SPLIT_A) ldsm4(sb + 16384 + off, al[mt]);
            }
#pragma unroll
            for (int np = 0; np < 4; ++np) {
                uint32_t boff = sw128((uint32_t)((n0 + np*16 + lrow) * 128 + kk*32 + lkb));
                uint32_t bh[4], bl[4];
                ldsm4(sb + 32768 + boff, bh);
                if (!SPLIT_A) ldsm4(sb + 16384 + boff, bl);
#pragma unroll
                for (int mt = 0; mt < 2; ++mt) {
                    if (SPLIT_A) {
                        mma_f16(acc[mt][2*np],   ah[mt], bh[0], bh[2]);
                        mma_f16(acc[mt][2*np],   al[mt], bh[0], bh[2]);
                        mma_f16(acc[mt][2*np+1], ah[mt], bh[1], bh[3]);
                        mma_f16(acc[mt][2*np+1], al[mt], bh[1], bh[3]);
                    } else {
                        mma_f16(acc[mt][2*np],   ah[mt], bh[0], bh[2]);
                        mma_f16(acc[mt][2*np],   ah[mt], bl[0], bl[2]);
                        mma_f16(acc[mt][2*np+1], ah[mt], bh[1], bh[3]);
                        mma_f16(acc[mt][2*np+1], ah[mt], bl[1], bl[3]);
                    }
                }
            }
        }
        __syncthreads();
        if (c + 2 < NC) issue(c + 2);
        else asm volatile("cp.async.commit_group;" ::: "memory");
    }

    // epilogue
    const int er = lane >> 2;
    const int ec = (lane & 3) * 2;
#pragma unroll
    for (int mt = 0; mt < 2; ++mt) {
#pragma unroll
        for (int nt = 0; nt < 8; ++nt) {
            const int row = bm + m0 + mt*16 + er;
            const int col = bn + n0 + nt*8 + ec;
            if (col < Nout) {
                float2 lo = { acc[mt][nt][0], acc[mt][nt][1] };
                float2 hi = { acc[mt][nt][2], acc[mt][nt][3] };
                *(float2*)(C + (size_t)row * Nout + col)       = lo;
                *(float2*)(C + (size_t)(row + 8) * Nout + col) = hi;
            }
        }
    }
}

// ---------------------------------------------------------------------------
// fp32 -> fp16 hi/lo splitter and single-fp16 converter (grid-stride, float4)
// ---------------------------------------------------------------------------
__global__ void split2_kernel(const float* __restrict__ s,
                              __half* __restrict__ h, __half* __restrict__ l, int n4)
{
    for (int i = blockIdx.x * blockDim.x + threadIdx.x; i < n4;
         i += gridDim.x * blockDim.x) {
        float4 v = ((const float4*)s)[i];
        __half hx = __float2half_rn(v.x), hy = __float2half_rn(v.y);
        __half hz = __float2half_rn(v.z), hw = __float2half_rn(v.w);
        __half lx = __float2half_rn(v.x - __half2float(hx));
        __half ly = __float2half_rn(v.y - __half2float(hy));
        __half lz = __float2half_rn(v.z - __half2float(hz));
        __half lw = __float2half_rn(v.w - __half2float(hw));
        __half2 h01 = __halves2half2(hx, hy), h23 = __halves2half2(hz, hw);
        __half2 l01 = __halves2half2(lx, ly), l23 = __halves2half2(lz, lw);
        ((uint2*)h)[i] = make_uint2(*(uint32_t*)&h01, *(uint32_t*)&h23);
        ((uint2*)l)[i] = make_uint2(*(uint32_t*)&l01, *(uint32_t*)&l23);
    }
}

__global__ void tof16_kernel(const float* __restrict__ s, __half* __restrict__ h, int n4)
{
    for (int i = blockIdx.x * blockDim.x + threadIdx.x; i < n4;
         i += gridDim.x * blockDim.x) {
        float4 v = ((const float4*)s)[i];
        __half2 h01 = __halves2half2(__float2half_rn(v.x), __float2half_rn(v.y));
        __half2 h23 = __halves2half2(__float2half_rn(v.z), __float2half_rn(v.w));
        ((uint2*)h)[i] = make_uint2(*(uint32_t*)&h01, *(uint32_t*)&h23);
    }
}

// xproj weights: pad 80 -> 128 rows (zeros), single fp16, both dirs.
__global__ void padw_kernel(const float* __restrict__ wf, const float* __restrict__ wb)
{
    const int total4 = 2 * 128 * CDI / 4;
    for (int i = blockIdx.x * blockDim.x + threadIdx.x; i < total4;
         i += gridDim.x * blockDim.x) {
        int e = i * 4;
        int dir = e / (128 * CDI);
        int rem = e - dir * 128 * CDI;
        int row = rem / CDI;
        int k   = rem - row * CDI;
        float4 v = {0.f, 0.f, 0.f, 0.f};
        const float* W = dir ? wb : wf;
        if (row < CPROJ) v = *(const float4*)(W + (size_t)row * CDI + k);
        __half2 h01 = __halves2half2(__float2half_rn(v.x), __float2half_rn(v.y));
        __half2 h23 = __halves2half2(__float2half_rn(v.z), __float2half_rn(v.w));
        ((uint2*)&g_wx[0][0])[i] = make_uint2(*(uint32_t*)&h01, *(uint32_t*)&h23);
    }
}

// ---------------------------------------------------------------------------
// Depthwise causal conv (K=4) + bias + SiLU, transpose to (b,t,d).
// Emits fp16 hi/lo xt (GEMM operand + scan input; hi+lo reconstructs to 2^-22).
// ---------------------------------------------------------------------------
__global__ void __launch_bounds__(256) conv_silu_kernel(
    const float* __restrict__ cw_f, const float* __restrict__ cb_f,
    const float* __restrict__ cw_b, const float* __restrict__ cb_b)
{
    const int t0 = blockIdx.x * 128;
    const int d0 = blockIdx.y * 32;
    const int b   = blockIdx.z & 1;
    const int dir = blockIdx.z >> 1;

    __shared__ float xs[32][133];

    const float* xbase = g_xz + ((size_t)b * (2*CDI) + d0) * CL;
    const int base = (dir == 0) ? (t0 - 3) : (CL - 128 - t0);

    const int lane = threadIdx.x & 31;
    const int wy   = threadIdx.x >> 5;
    for (int d = wy; d < 32; d += 8) {
        const float* row = xbase + (size_t)d * CL;
        for (int i = lane; i < 131; i += 32) {
            int u = base + i;
            xs[d][i] = (u >= 0 && u < CL) ? row[u] : 0.f;
        }
    }
    __syncthreads();

    const int d  = threadIdx.x & 31;
    const int sg = threadIdx.x >> 5;
    const float* cw = dir ? cw_b : cw_f;
    const float* cb = dir ? cb_b : cb_f;
    const float w0 = cw[(d0+d)*CK + 0];
    const float w1 = cw[(d0+d)*CK + 1];
    const float w2 = cw[(d0+d)*CK + 2];
    const float w3 = cw[(d0+d)*CK + 3];
    const float bias = cb[d0+d];

    __half* oh = g_xth[dir] + (size_t)b * CL * CDI;
    __half* ol = g_xtl[dir] + (size_t)b * CL * CDI;
#pragma unroll
    for (int q = 0; q < 16; ++q) {
        int s = sg + 8*q;
        float v;
        if (dir == 0) {
            v = w0*xs[d][s] + w1*xs[d][s+1] + w2*xs[d][s+2] + w3*xs[d][s+3] + bias;
        } else {
            v = w3*xs[d][127-s] + w2*xs[d][127-s+1] + w1*xs[d][127-s+2] + w0*xs[d][127-s+3] + bias;
        }
        float sv = v / (1.f + __expf(-v));
        size_t idx = (size_t)(t0 + s) * CDI + d0 + d;
        __half hb = __float2half_rn(sv);
        oh[idx] = hb;
        ol[idx] = __float2half_rn(sv - __half2float(hb));
    }
}

// ---------------------------------------------------------------------------
// dtproj + softplus
// ---------------------------------------------------------------------------
__device__ __forceinline__ float softplus_f(float v) {
    return (v > 20.f) ? v : log1pf(__expf(v));
}

__global__ void __launch_bounds__(256) dtproj_kernel(
    const float* __restrict__ dtw_f, const float* __restrict__ dtb_f,
    const float* __restrict__ dtw_b, const float* __restrict__ dtb_b)
{
    const int dir = blockIdx.z;
    const float* W    = dir ? dtw_b : dtw_f;
    const float* bias = dir ? dtb_b : dtb_f;
    const float* DT = g_dbl[dir];
    float* O = g_delta[dir];

    const int r0 = blockIdx.x * 64;
    const int d0 = blockIdx.y * 128;

    __shared__ __align__(16) float Ts[48][64];
    __shared__ __align__(16) float Ws2[48][128];

    const int tid = threadIdx.x;
#pragma unroll
    for (int p = 0; p < 3; ++p) {
        int q = tid + p*256;
        int rr = q / 12, kk = (q % 12) * 4;
        float4 v = *(const float4*)(DT + (size_t)(r0+rr)*CPROJ + kk);
        Ts[kk+0][rr]=v.x; Ts[kk+1][rr]=v.y; Ts[kk+2][rr]=v.z; Ts[kk+3][rr]=v.w;
    }
#pragma unroll
    for (int p = 0; p < 6; ++p) {
        int q = tid + p*256;
        int dd = q / 12, kk = (q % 12) * 4;
        float4 v = *(const float4*)(W + (size_t)(d0+dd)*CR + kk);
        Ws2[kk+0][dd]=v.x; Ws2[kk+1][dd]=v.y; Ws2[kk+2][dd]=v.z; Ws2[kk+3][dd]=v.w;
    }
    __syncthreads();

    const int tx = tid & 31;
    const int ty = tid >> 5;
    float acc[8][4] = {};
#pragma unroll
    for (int k = 0; k < 48; ++k) {
        float4 a0 = *(const float4*)&Ts[k][ty*8];
        float4 a1 = *(const float4*)&Ts[k][ty*8+4];
        float a[8] = {a0.x,a0.y,a0.z,a0.w,a1.x,a1.y,a1.z,a1.w};
        float4 w = *(const float4*)&Ws2[k][tx*4];
        float ww[4] = {w.x, w.y, w.z, w.w};
#pragma unroll
        for (int i = 0; i < 8; ++i)
#pragma unroll
            for (int j = 0; j < 4; ++j)
                acc[i][j] = fmaf(a[i], ww[j], acc[i][j]);
    }

    const int tx4 = tx*4;
    float b0 = bias[d0+tx4+0], b1 = bias[d0+tx4+1], b2 = bias[d0+tx4+2], b3 = bias[d0+tx4+3];
#pragma unroll
    for (int i = 0; i < 8; ++i) {
        float4 v;
        v.x = softplus_f(acc[i][0] + b0);
        v.y = softplus_f(acc[i][1] + b1);
        v.z = softplus_f(acc[i][2] + b2);
        v.w = softplus_f(acc[i][3] + b3);
        *(float4*)(O + (size_t)(r0 + ty*8 + i)*CDI + d0 + tx4) = v;
    }
}

// ---------------------------------------------------------------------------
// Selective scan (warp = 2 channels x 16 states); x from fp16 hi/lo pair.
// ---------------------------------------------------------------------------
__global__ void __launch_bounds__(256) scan_kernel(
    const float* __restrict__ Alog_f, const float* __restrict__ Dv_f,
    const float* __restrict__ Alog_b, const float* __restrict__ Dv_b)
{
    const int dir = blockIdx.z;
    const int b   = blockIdx.y;
    const int d0  = blockIdx.x * 16;

    const float* Alog = dir ? Alog_b : Alog_f;
    const float* Dvec = dir ? Dv_b   : Dv_f;
    const float* delta = g_delta[dir] + (size_t)b * CL * CDI;
    const __half* xth  = g_xth[dir]   + (size_t)b * CL * CDI;
    const __half* xtl  = g_xtl[dir]   + (size_t)b * CL * CDI;
    const float* dbl   = g_dbl[dir]   + (size_t)b * CL * CPROJ;
    float* yout        = g_y[dir]     + (size_t)b * CL * CDI;

    __shared__ __align__(16) float sd[64][16];
    __shared__ __align__(16) float sx[64][16];
    __shared__ __align__(16) float sB[64][16];
    __shared__ __align__(16) float sC[64][16];

    const int tid  = threadIdx.x;
    const int lane = tid & 31;
    const int wid  = tid >> 5;
    const int half = lane >> 4;
    const int n    = lane & 15;
    const int ch   = wid*2 + half;
    const int d    = d0 + ch;

    const float Aval = -__expf(Alog[d*CN + n]);
    const float Dval = Dvec[d];
    float h = 0.f;

    const int li = tid >> 2;
    const int lj = (tid & 3) * 4;

    float4 rd, rB, rC, rx;
    auto LD = [&](int t0) {
        rd = *(const float4*)(delta + (size_t)(t0+li)*CDI + d0 + lj);
        uint2 xh = *(const uint2*)(xth + (size_t)(t0+li)*CDI + d0 + lj);
        uint2 xl = *(const uint2*)(xtl + (size_t)(t0+li)*CDI + d0 + lj);
        __half2 h01 = *(__half2*)&xh.x, h23 = *(__half2*)&xh.y;
        __half2 l01 = *(__half2*)&xl.x, l23 = *(__half2*)&xl.y;
        float2 fh01 = __half22float2(h01), fh23 = __half22float2(h23);
        float2 fl01 = __half22float2(l01), fl23 = __half22float2(l23);
        rx.x = fh01.x + fl01.x; rx.y = fh01.y + fl01.y;
        rx.z = fh23.x + fl23.x; rx.w = fh23.y + fl23.y;
        rB = *(const float4*)(dbl + (size_t)(t0+li)*CPROJ + CR + lj);
        rC = *(const float4*)(dbl + (size_t)(t0+li)*CPROJ + CR + CN + lj);
    };
    LD(0);

    const int NCH = CL / 64;
    for (int c = 0; c < NCH; ++c) {
        __syncthreads();
        *(float4*)&sd[li][lj] = rd;
        *(float4*)&sx[li][lj] = rx;
        *(float4*)&sB[li][lj] = rB;
        *(float4*)&sC[li][lj] = rC;
        __syncthreads();
        if (c + 1 < NCH) LD((c+1) * 64);

        const int tbase = c * 64;
#pragma unroll 8
        for (int s = 0; s < 64; ++s) {
            float dt = sd[s][ch];
            float xv = sx[s][ch];
            float Bv = sB[s][n];
            float Cv = sC[s][n];
            float a = __expf(dt * Aval);
            h = fmaf(a, h, dt * xv * Bv);
            float p = h * Cv;
            p += __shfl_xor_sync(0xffffffffu, p, 8);
            p += __shfl_xor_sync(0xffffffffu, p, 4);
            p += __shfl_xor_sync(0xffffffffu, p, 2);
            p += __shfl_xor_sync(0xffffffffu, p, 1);
            if (n == 0)
                yout[(size_t)(tbase + s)*CDI + d] = p + xv * Dval;
        }
    }
}

// ---------------------------------------------------------------------------
// Gate + direction merge -> fp16 hi/lo comb (out_proj split operand)
// ---------------------------------------------------------------------------
__global__ void __launch_bounds__(256) combine_kernel()
{
    const int l0 = blockIdx.x * 32;
    const int d0 = blockIdx.y * 32;
    const int b  = blockIdx.z;

    __shared__ float zs[32][33];
    const int lane = threadIdx.x & 31;
    const int wy   = threadIdx.x >> 5;

    const float* zbase = g_xz + ((size_t)b * (2*CDI) + CDI + d0) * CL;
    for (int dd = wy; dd < 32; dd += 8)
        zs[dd][lane] = zbase[(size_t)dd * CL + l0 + lane];
    __syncthreads();

#pragma unroll
    for (int q = 0; q < 4; ++q) {
        int lr = wy + 8*q;
        int l = l0 + lr;
        size_t idx  = ((size_t)b*CL + l)*CDI + d0 + lane;
        size_t idxr = ((size_t)b*CL + (CL-1-l))*CDI + d0 + lane;
        float yf = g_y[0][idx];
        float yb = g_y[1][idxr];
        float zv = zs[lane][lr];
        float s = zv / (1.f + __expf(-zv));
        float cv = (yf + yb) * s;
        __half hb = __float2half_rn(cv);
        g_cmb_h[idx] = hb;
        g_cmb_l[idx] = __float2half_rn(cv - __half2float(hb));
    }
}

// ---------------------------------------------------------------------------
// Launcher
// ---------------------------------------------------------------------------
extern "C" void kernel_launch(void* const* d_in, const int* in_sizes, int n_in,
                              void* d_out, int out_size)
{
    (void)in_sizes; (void)n_in; (void)out_size;

    const float* hidden  = (const float*)d_in[0];
    const float* in_w    = (const float*)d_in[1];
    const float* conv_w  = (const float*)d_in[2];
    const float* conv_b  = (const float*)d_in[3];
    const float* xproj_w = (const float*)d_in[4];
    const float* dtw     = (const float*)d_in[5];
    const float* dtb     = (const float*)d_in[6];
    const float* A_log   = (const float*)d_in[7];
    const float* Dv      = (const float*)d_in[8];
    const float* conv_w2 = (const float*)d_in[9];
    const float* conv_b2 = (const float*)d_in[10];
    const float* xproj_w2= (const float*)d_in[11];
    const float* dtw2    = (const float*)d_in[12];
    const float* dtb2    = (const float*)d_in[13];
    const float* A_log2  = (const float*)d_in[14];
    const float* Dv2     = (const float*)d_in[15];
    const float* out_w   = (const float*)d_in[16];

    void *p_xz, *p_dbl;
    void *p_hid_h, *p_hid_l, *p_w1, *p_w2, *p_wx, *p_xth, *p_xtl, *p_cmb_h, *p_cmb_l;
    cudaGetSymbolAddress(&p_xz, g_xz);
    cudaGetSymbolAddress(&p_dbl, g_dbl);
    cudaGetSymbolAddress(&p_hid_h, g_hid_h);
    cudaGetSymbolAddress(&p_hid_l, g_hid_l);
    cudaGetSymbolAddress(&p_w1, g_w1);
    cudaGetSymbolAddress(&p_w2, g_w2);
    cudaGetSymbolAddress(&p_wx, g_wx);
    cudaGetSymbolAddress(&p_xth, g_xth);
    cudaGetSymbolAddress(&p_xtl, g_xtl);
    cudaGetSymbolAddress(&p_cmb_h, g_cmb_h);
    cudaGetSymbolAddress(&p_cmb_l, g_cmb_l);

    cudaFuncSetAttribute(gemm_f16_kernel<0>,
                         cudaFuncAttributeMaxDynamicSharedMemorySize, GF_SMEM);
    cudaFuncSetAttribute(gemm_f16_kernel<1>,
                         cudaFuncAttributeMaxDynamicSharedMemorySize, GF_SMEM);

    // 0) operand packing
    split2_kernel<<<1024, 256>>>(hidden, (__half*)p_hid_h, (__half*)p_hid_l, CB*CL*CDM/4);
    tof16_kernel<<<512, 256>>>(in_w, (__half*)p_w1, 2*CDI*CDM/4);
    tof16_kernel<<<512, 256>>>(out_w, (__half*)p_w2, CDM*CDI/4);
    padw_kernel<<<512, 256>>>(xproj_w, xproj_w2);

    // 1) in_proj: A = w1 (single), B = hidden (split).  M=3072, N=4096, K=768
    gemm_f16_kernel<0><<<dim3(CL/128, (2*CDI)/128, CB), 256, GF_SMEM>>>(
        (const __half*)p_w1, (const __half*)p_hid_l, (const __half*)p_hid_h,
        (float*)p_xz, CL, CDM,
        0, (long long)CL * CDM, (long long)(2*CDI) * CL, CDM / 64);

    // 2) conv + SiLU + transpose -> fp16 hi/lo xt
    conv_silu_kernel<<<dim3(CL/128, CDI/32, 2*CB), 256>>>(
        conv_w, conv_b, conv_w2, conv_b2);

    // 3) xproj: A = xt (split), B = wx (single).  M=8192 rows, N=80(pad128), K=1536
    gemm_f16_kernel<1><<<dim3(1, (CB*CL)/128, 2), 256, GF_SMEM>>>(
        (const __half*)p_xth, (const __half*)p_xtl, (const __half*)p_wx,
        (float*)p_dbl, CPROJ, CDI,
        (long long)CB*CL*CDI, (long long)128*CDI, (long long)CB*CL*CPROJ, CDI / 64);

    // 4) dtproj + softplus -> delta
    dtproj_kernel<<<dim3((CB*CL)/64, CDI/128, 2), 256>>>(dtw, dtb, dtw2, dtb2);

    // 5) selective scan
    scan_kernel<<<dim3(CDI/16, CB, 2), 256>>>(A_log, Dv, A_log2, Dv2);

    // 6) gate + direction merge -> fp16 hi/lo comb
    combine_kernel<<<dim3(CL/32, CDI/32, CB), 256>>>();

    // 7) out_proj: A = comb (split), B = w2 (single).  M=8192, N=768, K=1536
    gemm_f16_kernel<1><<<dim3(CDM/128, (CB*CL)/128, 1), 256, GF_SMEM>>>(
        (const __half*)p_cmb_h, (const __half*)p_cmb_l, (const __half*)p_w2,
        (float*)d_out, CDM, CDI,
        0, 0, 0, CDI / 64);
}